// round 4
// baseline (speedup 1.0000x reference)
#include <cuda_runtime.h>
#include <cuda_bf16.h>
#include <math.h>

// Problem dims
#define TT 16
#define BB 32
#define NN 512
#define FF 128
#define EE 2048            // F*T
#define MROWS 16384        // B*N
#define ATT_ELEMS (32*512*512)
#define RES_ELEMS (16*512*128)

// ---------------- device scratch (no allocations allowed) ----------------
__device__ float g_XR[(size_t)MROWS * EE];     // [B*N, E]  xr
__device__ float g_Q [(size_t)MROWS * EE];
__device__ float g_K [(size_t)MROWS * EE];
__device__ float g_V [(size_t)MROWS * EE];
__device__ float g_Att[(size_t)ATT_ELEMS];     // fallback attention buffer
__device__ float g_Abar[(size_t)512 * 512];    // [b*16+g, 512]
__device__ float g_Obar[(size_t)512 * EE];     // [512, 2048]
__device__ float g_OutBar[(size_t)512 * EE];   // [512, 2048]

// ---------------- 1) build XR[b*512+n, f*16+t] = x[t,b,n,f] ----------------
__global__ void __launch_bounds__(256) build_xr(const float* __restrict__ x,
                                                float* __restrict__ xr) {
    __shared__ float s[TT * 129];   // [t][f] padded
    int bn = blockIdx.x;            // b*512+n
    int b = bn >> 9, n = bn & 511;
    for (int i = threadIdx.x; i < TT * FF; i += 256) {
        int t = i >> 7, f = i & 127;
        s[t * 129 + f] = x[((size_t)(t * BB + b) * NN + n) * FF + f];
    }
    __syncthreads();
    for (int e = threadIdx.x; e < EE; e += 256) {
        int t = e & 15, f = e >> 4;
        xr[(size_t)bn * EE + e] = s[t * 129 + f];
    }
}

// ---------------- 2) generic NT GEMM: C = scale*(A[M,K] @ B[N,K]^T) + bias ----------------
// All dims multiples of 128 (K multiple of 16). blockIdx.z = batch with strides.
__global__ void __launch_bounds__(256, 2) gemm_nt(
    const float* __restrict__ A, const float* __restrict__ B,
    const float* __restrict__ bias, float* __restrict__ C,
    int M, int N, int K,
    long long sA, long long sB, long long sC, float scale)
{
    const int BM = 128, BN = 128, BK = 16;
    A += (long long)blockIdx.z * sA;
    B += (long long)blockIdx.z * sB;
    C += (long long)blockIdx.z * sC;

    __shared__ float As[BK][BM + 4];
    __shared__ float Bs[BK][BN + 4];

    int tid = threadIdx.x;
    int row0 = blockIdx.y * BM, col0 = blockIdx.x * BN;
    int tx = tid & 15, ty = tid >> 4;

    float acc[8][8];
#pragma unroll
    for (int i = 0; i < 8; i++)
#pragma unroll
        for (int j = 0; j < 8; j++) acc[i][j] = 0.f;

    for (int kt = 0; kt < K; kt += BK) {
#pragma unroll
        for (int it = 0; it < 2; it++) {
            int idx = tid + it * 256;
            int r = idx >> 2;
            int q = (idx & 3) * 4;
            float4 a4 = *(const float4*)(A + (size_t)(row0 + r) * K + kt + q);
            As[q + 0][r] = a4.x; As[q + 1][r] = a4.y;
            As[q + 2][r] = a4.z; As[q + 3][r] = a4.w;
            float4 b4 = *(const float4*)(B + (size_t)(col0 + r) * K + kt + q);
            Bs[q + 0][r] = b4.x; Bs[q + 1][r] = b4.y;
            Bs[q + 2][r] = b4.z; Bs[q + 3][r] = b4.w;
        }
        __syncthreads();
#pragma unroll
        for (int k = 0; k < BK; k++) {
            float ar[8], br[8];
            *(float4*)(ar)     = *(const float4*)&As[k][ty * 8];
            *(float4*)(ar + 4) = *(const float4*)&As[k][ty * 8 + 4];
            *(float4*)(br)     = *(const float4*)&Bs[k][tx * 8];
            *(float4*)(br + 4) = *(const float4*)&Bs[k][tx * 8 + 4];
#pragma unroll
            for (int i = 0; i < 8; i++)
#pragma unroll
                for (int j = 0; j < 8; j++)
                    acc[i][j] = fmaf(ar[i], br[j], acc[i][j]);
        }
        __syncthreads();
    }

#pragma unroll
    for (int i = 0; i < 8; i++) {
        size_t crow = (size_t)(row0 + ty * 8 + i) * N + col0;
#pragma unroll
        for (int j = 0; j < 8; j += 4) {
            int c = tx * 8 + j;
            float4 o;
            o.x = acc[i][j + 0] * scale + (bias ? bias[col0 + c + 0] : 0.f);
            o.y = acc[i][j + 1] * scale + (bias ? bias[col0 + c + 1] : 0.f);
            o.z = acc[i][j + 2] * scale + (bias ? bias[col0 + c + 2] : 0.f);
            o.w = acc[i][j + 3] * scale + (bias ? bias[col0 + c + 3] : 0.f);
            *(float4*)(C + crow + c) = o;
        }
    }
}

// ---------------- 3) row softmax (in place), rows of 512 ----------------
__global__ void __launch_bounds__(128) softmax_rows(float* __restrict__ att) {
    size_t row = blockIdx.x;
    float4* p = (float4*)(att + row * 512);
    float4 v = p[threadIdx.x];
    float m = fmaxf(fmaxf(v.x, v.y), fmaxf(v.z, v.w));
#pragma unroll
    for (int o = 16; o; o >>= 1) m = fmaxf(m, __shfl_xor_sync(0xffffffffu, m, o));
    __shared__ float sm[4];
    if ((threadIdx.x & 31) == 0) sm[threadIdx.x >> 5] = m;
    __syncthreads();
    m = fmaxf(fmaxf(sm[0], sm[1]), fmaxf(sm[2], sm[3]));
    v.x = __expf(v.x - m); v.y = __expf(v.y - m);
    v.z = __expf(v.z - m); v.w = __expf(v.w - m);
    float s = v.x + v.y + v.z + v.w;
#pragma unroll
    for (int o = 16; o; o >>= 1) s += __shfl_xor_sync(0xffffffffu, s, o);
    __shared__ float ss[4];
    if ((threadIdx.x & 31) == 0) ss[threadIdx.x >> 5] = s;
    __syncthreads();
    s = ss[0] + ss[1] + ss[2] + ss[3];
    float inv = 1.f / s;
    v.x *= inv; v.y *= inv; v.z *= inv; v.w *= inv;
    p[threadIdx.x] = v;
}

// ---------------- 4) Abar[b*16+g, j] = mean over 32 att rows ----------------
__global__ void __launch_bounds__(512) abar_kernel(const float* __restrict__ att,
                                                   float* __restrict__ abar) {
    int bg = blockIdx.x;               // b*16+g
    int b = bg >> 4, g = bg & 15;
    const float* base = att + ((size_t)b * 512 + g * 32) * 512;
    int j = threadIdx.x;
    float s = 0.f;
#pragma unroll 8
    for (int r = 0; r < 32; r++) s += base[(size_t)r * 512 + j];
    abar[(size_t)bg * 512 + j] = s * (1.f / 32.f);
}

// ---------------- 5) Obar[b*16+g, :] = Abar_b @ V_b  (16x2048 per batch) ----------------
__global__ void __launch_bounds__(128) obar_kernel(const float* __restrict__ abar,
                                                   const float* __restrict__ V,
                                                   float* __restrict__ obar) {
    int b = blockIdx.y;
    int col0 = blockIdx.x * 128;
    __shared__ float sA[16 * 512];     // 32 KB
    for (int i = threadIdx.x; i < 16 * 512; i += 128)
        sA[i] = abar[(size_t)b * 16 * 512 + i];
    __syncthreads();
    float acc[16];
#pragma unroll
    for (int g = 0; g < 16; g++) acc[g] = 0.f;
    const float* vb = V + (size_t)b * 512 * EE + col0 + threadIdx.x;
    for (int l = 0; l < 512; l++) {
        float vv = vb[(size_t)l * EE];
#pragma unroll
        for (int g = 0; g < 16; g++) acc[g] = fmaf(sA[g * 512 + l], vv, acc[g]);
    }
#pragma unroll
    for (int g = 0; g < 16; g++)
        obar[((size_t)b * 16 + g) * EE + col0 + threadIdx.x] = acc[g];
}

// ---------------- 6) final: result[t,i,f] = mean_b x[t,b,i,f] + OutBar[i, t*128+f] ----------------
__global__ void __launch_bounds__(256) final_kernel(const float* __restrict__ x,
                                                    const float* __restrict__ outbar,
                                                    float* __restrict__ out) {
    int idx = blockIdx.x * 256 + threadIdx.x;   // < 1048576
    int f = idx & 127;
    int i = (idx >> 7) & 511;
    int t = idx >> 16;
    const float* px = x + (size_t)t * (BB * NN * FF) + (size_t)i * FF + f;
    float s = 0.f;
#pragma unroll 8
    for (int b = 0; b < 32; b++) s += px[(size_t)b * (NN * FF)];
    out[idx] = s * (1.f / 32.f) + outbar[(size_t)i * EE + t * FF + f];
}

// ---------------- launcher ----------------
extern "C" void kernel_launch(void* const* d_in, const int* in_sizes, int n_in,
                              void* d_out, int out_size) {
    const float* x   = (const float*)d_in[0];
    const float* Wq  = (const float*)d_in[1];
    const float* bq  = (const float*)d_in[2];
    const float* Wk  = (const float*)d_in[3];
    const float* bk  = (const float*)d_in[4];
    const float* Wv  = (const float*)d_in[5];
    const float* bv  = (const float*)d_in[6];
    const float* Wfc = (const float*)d_in[7];
    const float* bfc = (const float*)d_in[8];
    float* out = (float*)d_out;

    float *pXR, *pQ, *pK, *pV, *pAtt, *pAbar, *pObar, *pOutBar;
    cudaGetSymbolAddress((void**)&pXR, g_XR);
    cudaGetSymbolAddress((void**)&pQ, g_Q);
    cudaGetSymbolAddress((void**)&pK, g_K);
    cudaGetSymbolAddress((void**)&pV, g_V);
    cudaGetSymbolAddress((void**)&pAbar, g_Abar);
    cudaGetSymbolAddress((void**)&pObar, g_Obar);
    cudaGetSymbolAddress((void**)&pOutBar, g_OutBar);

    // attention goes straight into d_out when the harness checks the tuple
    if (out_size >= RES_ELEMS + ATT_ELEMS) pAtt = out + RES_ELEMS;
    else cudaGetSymbolAddress((void**)&pAtt, g_Att);

    // 1) xr
    build_xr<<<MROWS, 256>>>(x, pXR);

    // 2) Q, K, V  (NT GEMMs, M=16384, N=K=2048)
    dim3 gBig(EE / 128, MROWS / 128, 1);
    gemm_nt<<<gBig, 256>>>(pXR, Wq, bq, pQ, MROWS, EE, EE, 0, 0, 0, 1.f);
    gemm_nt<<<gBig, 256>>>(pXR, Wk, bk, pK, MROWS, EE, EE, 0, 0, 0, 1.f);
    gemm_nt<<<gBig, 256>>>(pXR, Wv, bv, pV, MROWS, EE, EE, 0, 0, 0, 1.f);

    // 3) energy (scaled), batched over 32: C_b = (Q_b K_b^T)/sqrt(E)
    dim3 gE(512 / 128, 512 / 128, 32);
    float scale = rsqrtf((float)EE);
    gemm_nt<<<gE, 256>>>(pQ, pK, nullptr, pAtt, 512, 512, EE,
                         (long long)512 * EE, (long long)512 * EE,
                         (long long)512 * 512, scale);

    // 4) softmax in place -> attention output
    softmax_rows<<<32 * 512, 128>>>(pAtt);

    // 5) group-mean attention rows
    abar_kernel<<<512, 512>>>(pAtt, pAbar);

    // 6) Obar = Abar_b @ V_b
    dim3 gO(EE / 128, 32);
    obar_kernel<<<gO, 128>>>(pAbar, pV, pObar);

    // 7) FC on the reduced rows: OutBar = Obar @ Wfc^T + bfc  (512x2048x2048)
    dim3 gFC(EE / 128, 512 / 128, 1);
    gemm_nt<<<gFC, 256>>>(pObar, Wfc, bfc, pOutBar, 512, EE, EE, 0, 0, 0, 1.f);

    // 8) final output
    final_kernel<<<RES_ELEMS / 256, 256>>>(x, pOutBar, out);
}

// round 7
// speedup vs baseline: 3.2200x; 3.2200x over previous
#include <cuda_runtime.h>
#include <cuda_bf16.h>
#include <math.h>
#include <stdint.h>

// Problem dims
#define TT 16
#define BB 32
#define NN 512
#define FF 128
#define EE 2048            // F*T
#define K3 6144            // 3*EE  (split-bf16 concatenated K)
#define MROWS 16384        // B*N
#define ATT_ELEMS (32*512*512)
#define RES_ELEMS (16*512*128)

// ---------------- device scratch (no allocations allowed) ----------------
__device__ float g_XR[(size_t)MROWS * EE];          // [B*N, E]
__device__ float g_Yf[(size_t)MROWS * EE];          // Y = XR @ M3^T
__device__ float g_M3f[(size_t)EE * EE];            // M3 = Wk^T Wq
__device__ float g_Att[(size_t)ATT_ELEMS];
__device__ float g_Abar[(size_t)512 * 512];
__device__ float g_Zf[(size_t)512 * EE];            // Z = Abar @ XR
__device__ float g_Obar[(size_t)512 * EE];
__device__ float g_OutBar[(size_t)512 * EE];
__device__ float g_w2[EE];
__device__ float g_vvec[MROWS];

// bf16 split operands: A-mode rows = [hi | lo | hi], B-mode rows = [hi | hi | lo]
__device__ __nv_bfloat16 g_XRsA[(size_t)MROWS * K3];
__device__ __nv_bfloat16 g_XRsB[(size_t)MROWS * K3];
__device__ __nv_bfloat16 g_Ys  [(size_t)MROWS * K3];
__device__ __nv_bfloat16 g_M3s [(size_t)EE * K3];
__device__ __nv_bfloat16 g_WkTs[(size_t)EE * K3];
__device__ __nv_bfloat16 g_WqTs[(size_t)EE * K3];
__device__ __nv_bfloat16 g_Wvs [(size_t)EE * K3];
__device__ __nv_bfloat16 g_Wfcs[(size_t)EE * K3];
__device__ __nv_bfloat16 g_Zs  [(size_t)512 * K3];
__device__ __nv_bfloat16 g_Obars[(size_t)512 * K3];

// ================= helpers =================
__device__ __forceinline__ uint32_t smem_u32(const void* p) {
    uint32_t a;
    asm("{ .reg .u64 t; cvta.to.shared.u64 t, %1; cvt.u32.u64 %0, t; }" : "=r"(a) : "l"(p));
    return a;
}
#define SWZ128(off) ((off) ^ (((off) >> 3) & 0x70))

__device__ __forceinline__ void cp16(uint32_t s, const void* g) {
    asm volatile("cp.async.cg.shared.global [%0], [%1], 16;" :: "r"(s), "l"(g));
}
#define CP_COMMIT() asm volatile("cp.async.commit_group;" ::: "memory")
#define CP_WAIT1()  asm volatile("cp.async.wait_group 1;" ::: "memory")

__device__ __forceinline__ void ldmx4(uint32_t* f, uint32_t addr) {
    asm volatile("ldmatrix.sync.aligned.m8n8.x4.shared.b16 {%0,%1,%2,%3}, [%4];"
        : "=r"(f[0]), "=r"(f[1]), "=r"(f[2]), "=r"(f[3]) : "r"(addr));
}
__device__ __forceinline__ void mma16816(float* d, const uint32_t* a,
                                         uint32_t b0, uint32_t b1) {
    asm volatile("mma.sync.aligned.m16n8k16.row.col.f32.bf16.bf16.f32 "
        "{%0,%1,%2,%3}, {%4,%5,%6,%7}, {%8,%9}, {%0,%1,%2,%3};"
        : "+f"(d[0]), "+f"(d[1]), "+f"(d[2]), "+f"(d[3])
        : "r"(a[0]), "r"(a[1]), "r"(a[2]), "r"(a[3]), "r"(b0), "r"(b1));
}

#define STAGE_BYTES 32768      // A 16KB + B 16KB (128 rows x 128B, 64 bf16 k-chunk)
#define DSM_BYTES (2 * STAGE_BYTES + 128)

// ================= bf16 mma.sync NT GEMM =================
// C[M,N] = scale*(A[M,K] @ B[N,K]^T) + bias. 128x128 tiles, BK=64 bf16.
// 256 threads = 8 warps: warp (wm=wid&3, wn=wid>>2) -> 32(m) x 64(n) warp tile.
__global__ void __launch_bounds__(256, 2)
gemm_mma_nt(const __nv_bfloat16* __restrict__ A, const __nv_bfloat16* __restrict__ B,
            const float* __restrict__ bias, float* __restrict__ C,
            int Ncols, int Kc, long long sA, long long sB, long long sC, float scale)
{
    extern __shared__ char sm[];
    A += (long long)blockIdx.z * sA;
    B += (long long)blockIdx.z * sB;
    C += (long long)blockIdx.z * sC;

    const int tid = threadIdx.x, wid = tid >> 5, lane = tid & 31;
    const int row0 = blockIdx.y * 128, col0 = blockIdx.x * 128;
    const int wm = wid & 3, wn = wid >> 2;

    uint32_t sbase = (smem_u32(sm) + 127u) & ~127u;

    // loader: thread -> row = tid>>1 (0..127), 4 x 16B chunks at (tid&1)*4
    const int lrow = tid >> 1;
    const int lc0 = (tid & 1) * 4;
    const char* gA = (const char*)(A + (long long)(row0 + lrow) * Kc);
    const char* gB = (const char*)(B + (long long)(col0 + lrow) * Kc);
    uint32_t swo[4];
#pragma unroll
    for (int q = 0; q < 4; q++) {
        uint32_t off = (uint32_t)lrow * 128u + (lc0 + q) * 16u;
        swo[q] = SWZ128(off);
    }

    const int nc = Kc / 64;

    // prologue: 2 stages
#pragma unroll
    for (int s = 0; s < 2; s++) {
        uint32_t aA = sbase + s * STAGE_BYTES;
        uint32_t aB = aA + 16384;
        long long kb = (long long)s * 128;
#pragma unroll
        for (int q = 0; q < 4; q++) {
            cp16(aA + swo[q], gA + kb + (lc0 + q) * 16);
            cp16(aB + swo[q], gB + kb + (lc0 + q) * 16);
        }
        CP_COMMIT();
    }

    float acc[2][8][4];
#pragma unroll
    for (int mi = 0; mi < 2; mi++)
#pragma unroll
        for (int ni = 0; ni < 8; ni++)
#pragma unroll
            for (int r = 0; r < 4; r++) acc[mi][ni][r] = 0.f;

    // fragment addresses (swizzled, depend only on lane)
    const int fr = lane & 15;               // row within 16-row tile
    const int fk = (lane >> 4) * 16;        // 0 or 16 bytes within 32B kstep

    for (int c = 0; c < nc; c++) {
        CP_WAIT1();
        __syncthreads();
        uint32_t aA = sbase + (c & 1) * STAGE_BYTES;
        uint32_t aB = aA + 16384;
#pragma unroll
        for (int ks = 0; ks < 4; ks++) {
            const int kbyte = ks * 32 + fk;
            uint32_t af[2][4];
#pragma unroll
            for (int mi = 0; mi < 2; mi++) {
                int r = wm * 32 + mi * 16 + fr;
                ldmx4(af[mi], aA + SWZ128((uint32_t)(r * 128 + kbyte)));
            }
#pragma unroll
            for (int bi = 0; bi < 4; bi++) {
                uint32_t bf[4];
                int r = wn * 64 + bi * 16 + fr;
                ldmx4(bf, aB + SWZ128((uint32_t)(r * 128 + kbyte)));
                // bf: {b0 of ntile 2bi, b0 of ntile 2bi+1, b1 of 2bi, b1 of 2bi+1}
#pragma unroll
                for (int mi = 0; mi < 2; mi++) {
                    mma16816(acc[mi][2 * bi + 0], af[mi], bf[0], bf[2]);
                    mma16816(acc[mi][2 * bi + 1], af[mi], bf[1], bf[3]);
                }
            }
        }
        __syncthreads();
        if (c + 2 < nc) {
            long long kb = (long long)(c + 2) * 128;
#pragma unroll
            for (int q = 0; q < 4; q++) {
                cp16(aA + swo[q], gA + kb + (lc0 + q) * 16);
                cp16(aB + swo[q], gB + kb + (lc0 + q) * 16);
            }
        }
        CP_COMMIT();
    }

    // epilogue
#pragma unroll
    for (int mi = 0; mi < 2; mi++) {
        int r = row0 + wm * 32 + mi * 16 + (lane >> 2);
#pragma unroll
        for (int ni = 0; ni < 8; ni++) {
            int cc = col0 + wn * 64 + ni * 8 + (lane & 3) * 2;
            float b0 = bias ? bias[cc] : 0.f;
            float b1 = bias ? bias[cc + 1] : 0.f;
            float2 v0, v1;
            v0.x = acc[mi][ni][0] * scale + b0;
            v0.y = acc[mi][ni][1] * scale + b1;
            v1.x = acc[mi][ni][2] * scale + b0;
            v1.y = acc[mi][ni][3] * scale + b1;
            *(float2*)(C + (long long)r * Ncols + cc) = v0;
            *(float2*)(C + (long long)(r + 8) * Ncols + cc) = v1;
        }
    }
}

// ================= split-bf16 conversion =================
// X fp32 [R,2048] -> Y bf16 [R,6144]; A-mode: [hi|lo|hi], B-mode: [hi|hi|lo]
__global__ void __launch_bounds__(256) split3(const float* __restrict__ X,
                                              __nv_bfloat16* __restrict__ Y,
                                              int n, int modeB) {
    int i = blockIdx.x * 256 + threadIdx.x;
    if (i >= n) return;
    int r = i >> 11, k = i & 2047;
    float x = X[i];
    __nv_bfloat16 h = __float2bfloat16(x);
    __nv_bfloat16 l = __float2bfloat16(x - __bfloat162float(h));
    __nv_bfloat16* yr = Y + (size_t)r * K3;
    yr[k] = h;
    yr[2048 + k] = modeB ? h : l;
    yr[4096 + k] = modeB ? l : h;
}

// transpose + split: Y[r, k] (split3 layout) = W[k, r],  W is [2048 x 2048]
__global__ void __launch_bounds__(256) split3t(const float* __restrict__ W,
                                               __nv_bfloat16* __restrict__ Y, int modeB) {
    __shared__ float t[32][33];
    int tx = threadIdx.x & 31, ty = threadIdx.x >> 5;   // 32 x 8
    int cbase = blockIdx.x * 32;   // out rows  (W cols)
    int rbase = blockIdx.y * 32;   // out k     (W rows)
#pragma unroll
    for (int j = 0; j < 4; j++)
        t[ty + j * 8][tx] = W[(size_t)(rbase + ty + j * 8) * EE + cbase + tx];
    __syncthreads();
#pragma unroll
    for (int j = 0; j < 4; j++) {
        int r = cbase + ty + j * 8;
        int k = rbase + tx;
        float x = t[tx][ty + j * 8];
        __nv_bfloat16 h = __float2bfloat16(x);
        __nv_bfloat16 l = __float2bfloat16(x - __bfloat162float(h));
        __nv_bfloat16* yr = Y + (size_t)r * K3;
        yr[k] = h;
        yr[2048 + k] = modeB ? h : l;
        yr[4096 + k] = modeB ? l : h;
    }
}

// ---------------- build XR[b*512+n, f*16+t] = x[t,b,n,f] ----------------
__global__ void __launch_bounds__(256) build_xr(const float* __restrict__ x,
                                                float* __restrict__ xr) {
    __shared__ float s[TT * 129];
    int bn = blockIdx.x;
    int b = bn >> 9, n = bn & 511;
    for (int i = threadIdx.x; i < TT * FF; i += 256) {
        int t = i >> 7, f = i & 127;
        s[t * 129 + f] = x[((size_t)(t * BB + b) * NN + n) * FF + f];
    }
    __syncthreads();
    for (int e = threadIdx.x; e < EE; e += 256) {
        int t = e & 15, f = e >> 4;
        xr[(size_t)bn * EE + e] = s[t * 129 + f];
    }
}

// ---------------- bias-path kernels: w2 = Wk^T bq, v = scale * XR @ w2 ----------------
__global__ void __launch_bounds__(256) wkbq_kernel(const float* __restrict__ Wk,
                                                   const float* __restrict__ bq,
                                                   float* __restrict__ w2) {
    int e = blockIdx.x * 256 + threadIdx.x;
    float s = 0.f;
    for (int d = 0; d < EE; d++) s += Wk[(size_t)d * EE + e] * bq[d];
    w2[e] = s;
}
__global__ void __launch_bounds__(256) xrw2_kernel(const float* __restrict__ XR,
                                                   const float* __restrict__ w2,
                                                   float* __restrict__ v, float scale) {
    int g = blockIdx.x * 8 + (threadIdx.x >> 5);
    int lane = threadIdx.x & 31;
    const float* r = XR + (size_t)g * EE;
    float s = 0.f;
    for (int e = lane; e < EE; e += 32) s += r[e] * w2[e];
#pragma unroll
    for (int o = 16; o; o >>= 1) s += __shfl_xor_sync(0xffffffffu, s, o);
    if (lane == 0) v[g] = s * scale;
}

// ---------------- row softmax with additive per-column vector ----------------
__global__ void __launch_bounds__(128) softmax_rows(float* __restrict__ att,
                                                    const float* __restrict__ vadd) {
    size_t row = blockIdx.x;
    int b = (int)(row >> 9);
    float4* p = (float4*)(att + row * 512);
    const float4* vv = (const float4*)(vadd + (size_t)b * 512);
    float4 v = p[threadIdx.x];
    float4 a = vv[threadIdx.x];
    v.x += a.x; v.y += a.y; v.z += a.z; v.w += a.w;
    float m = fmaxf(fmaxf(v.x, v.y), fmaxf(v.z, v.w));
#pragma unroll
    for (int o = 16; o; o >>= 1) m = fmaxf(m, __shfl_xor_sync(0xffffffffu, m, o));
    __shared__ float sm[4];
    if ((threadIdx.x & 31) == 0) sm[threadIdx.x >> 5] = m;
    __syncthreads();
    m = fmaxf(fmaxf(sm[0], sm[1]), fmaxf(sm[2], sm[3]));
    v.x = __expf(v.x - m); v.y = __expf(v.y - m);
    v.z = __expf(v.z - m); v.w = __expf(v.w - m);
    float s = v.x + v.y + v.z + v.w;
#pragma unroll
    for (int o = 16; o; o >>= 1) s += __shfl_xor_sync(0xffffffffu, s, o);
    __shared__ float ss[4];
    if ((threadIdx.x & 31) == 0) ss[threadIdx.x >> 5] = s;
    __syncthreads();
    s = ss[0] + ss[1] + ss[2] + ss[3];
    float inv = 1.f / s;
    v.x *= inv; v.y *= inv; v.z *= inv; v.w *= inv;
    p[threadIdx.x] = v;
}

// ---------------- Abar ----------------
__global__ void __launch_bounds__(512) abar_kernel(const float* __restrict__ att,
                                                   float* __restrict__ abar) {
    int bg = blockIdx.x;
    int b = bg >> 4, g = bg & 15;
    const float* bse = att + ((size_t)b * 512 + g * 32) * 512;
    int j = threadIdx.x;
    float s = 0.f;
#pragma unroll 8
    for (int r = 0; r < 32; r++) s += bse[(size_t)r * 512 + j];
    abar[(size_t)bg * 512 + j] = s * (1.f / 32.f);
}

// ---------------- Z[b*16+g,:] = Abar_b @ XR_b ----------------
__global__ void __launch_bounds__(128) zbar_kernel(const float* __restrict__ abar,
                                                   const float* __restrict__ XR,
                                                   float* __restrict__ z) {
    int b = blockIdx.y;
    int col0 = blockIdx.x * 128;
    __shared__ float sA[16 * 512];
    for (int i = threadIdx.x; i < 16 * 512; i += 128)
        sA[i] = abar[(size_t)b * 16 * 512 + i];
    __syncthreads();
    float acc[16];
#pragma unroll
    for (int g = 0; g < 16; g++) acc[g] = 0.f;
    const float* vb = XR + (size_t)b * 512 * EE + col0 + threadIdx.x;
    for (int l = 0; l < 512; l++) {
        float vv = vb[(size_t)l * EE];
#pragma unroll
        for (int g = 0; g < 16; g++) acc[g] = fmaf(sA[g * 512 + l], vv, acc[g]);
    }
#pragma unroll
    for (int g = 0; g < 16; g++)
        z[((size_t)b * 16 + g) * EE + col0 + threadIdx.x] = acc[g];
}

// ---------------- final ----------------
__global__ void __launch_bounds__(256) final_kernel(const float* __restrict__ x,
                                                    const float* __restrict__ outbar,
                                                    float* __restrict__ out) {
    int idx = blockIdx.x * 256 + threadIdx.x;
    int f = idx & 127;
    int i = (idx >> 7) & 511;
    int t = idx >> 16;
    const float* px = x + (size_t)t * (BB * NN * FF) + (size_t)i * FF + f;
    float s = 0.f;
#pragma unroll 8
    for (int b = 0; b < 32; b++) s += px[(size_t)b * (NN * FF)];
    out[idx] = s * (1.f / 32.f) + outbar[(size_t)i * EE + t * FF + f];
}

// ---------------- launcher ----------------
extern "C" void kernel_launch(void* const* d_in, const int* in_sizes, int n_in,
                              void* d_out, int out_size) {
    const float* x   = (const float*)d_in[0];
    const float* Wq  = (const float*)d_in[1];
    const float* bq  = (const float*)d_in[2];
    const float* Wk  = (const float*)d_in[3];
    const float* bk  = (const float*)d_in[4];   // unused (drops out of softmax)
    const float* Wv  = (const float*)d_in[5];
    const float* bv  = (const float*)d_in[6];
    const float* Wfc = (const float*)d_in[7];
    const float* bfc = (const float*)d_in[8];
    float* out = (float*)d_out;
    (void)bk;

    float *pXR, *pYf, *pM3f, *pAtt, *pAbar, *pZf, *pObar, *pOutBar, *pw2, *pv;
    __nv_bfloat16 *pXRsA, *pXRsB, *pYs, *pM3s, *pWkTs, *pWqTs, *pWvs, *pWfcs, *pZs, *pObars;
    cudaGetSymbolAddress((void**)&pXR, g_XR);
    cudaGetSymbolAddress((void**)&pYf, g_Yf);
    cudaGetSymbolAddress((void**)&pM3f, g_M3f);
    cudaGetSymbolAddress((void**)&pAbar, g_Abar);
    cudaGetSymbolAddress((void**)&pZf, g_Zf);
    cudaGetSymbolAddress((void**)&pObar, g_Obar);
    cudaGetSymbolAddress((void**)&pOutBar, g_OutBar);
    cudaGetSymbolAddress((void**)&pw2, g_w2);
    cudaGetSymbolAddress((void**)&pv, g_vvec);
    cudaGetSymbolAddress((void**)&pXRsA, g_XRsA);
    cudaGetSymbolAddress((void**)&pXRsB, g_XRsB);
    cudaGetSymbolAddress((void**)&pYs, g_Ys);
    cudaGetSymbolAddress((void**)&pM3s, g_M3s);
    cudaGetSymbolAddress((void**)&pWkTs, g_WkTs);
    cudaGetSymbolAddress((void**)&pWqTs, g_WqTs);
    cudaGetSymbolAddress((void**)&pWvs, g_Wvs);
    cudaGetSymbolAddress((void**)&pWfcs, g_Wfcs);
    cudaGetSymbolAddress((void**)&pZs, g_Zs);
    cudaGetSymbolAddress((void**)&pObars, g_Obars);

    if (out_size >= RES_ELEMS + ATT_ELEMS) pAtt = out + RES_ELEMS;
    else cudaGetSymbolAddress((void**)&pAtt, g_Att);

    cudaFuncSetAttribute(gemm_mma_nt, cudaFuncAttributeMaxDynamicSharedMemorySize, DSM_BYTES);

    const float scale = rsqrtf((float)EE);
    const int nXR = MROWS * EE;
    const int nW = EE * EE;

    // 1) xr + its splits
    build_xr<<<MROWS, 256>>>(x, pXR);
    split3<<<(nXR + 255) / 256, 256>>>(pXR, pXRsA, nXR, 0);
    split3<<<(nXR + 255) / 256, 256>>>(pXR, pXRsB, nXR, 1);

    // 2) M3 = Wk^T Wq : A = Wk^T (A-mode), B = Wq^T (B-mode)
    dim3 gT(64, 64);
    split3t<<<gT, 256>>>(Wk, pWkTs, 0);
    split3t<<<gT, 256>>>(Wq, pWqTs, 1);
    dim3 gM3(EE / 128, EE / 128);
    gemm_mma_nt<<<gM3, 256, DSM_BYTES>>>(pWkTs, pWqTs, nullptr, pM3f, EE, K3, 0, 0, 0, 1.f);
    split3<<<(nW + 255) / 256, 256>>>(pM3f, pM3s, nW, 1);

    // 3) Y = XR @ M3^T
    dim3 gY(EE / 128, MROWS / 128);
    gemm_mma_nt<<<gY, 256, DSM_BYTES>>>(pXRsA, pM3s, nullptr, pYf, EE, K3, 0, 0, 0, 1.f);
    split3<<<(nXR + 255) / 256, 256>>>(pYf, pYs, nXR, 0);

    // 4) energy core = scale * Y_b XR_b^T  (batched over 32)
    dim3 gE(512 / 128, 512 / 128, 32);
    gemm_mma_nt<<<gE, 256, DSM_BYTES>>>(pYs, pXRsB, nullptr, pAtt, 512, K3,
                                        (long long)512 * K3, (long long)512 * K3,
                                        (long long)512 * 512, scale);

    // 5) bias column vector v = scale * XR @ (Wk^T bq); softmax with +v[j]
    wkbq_kernel<<<EE / 256, 256>>>(Wk, bq, pw2);
    xrw2_kernel<<<MROWS / 8, 256>>>(pXR, pw2, pv, scale);
    softmax_rows<<<32 * 512, 128>>>(pAtt, pv);

    // 6) Abar, Z = Abar @ XR
    abar_kernel<<<512, 512>>>(pAtt, pAbar);
    dim3 gZ(EE / 128, 32);
    zbar_kernel<<<gZ, 128>>>(pAbar, pXR, pZf);

    // 7) Obar = Z @ Wv^T + bv
    split3<<<(512 * EE + 255) / 256, 256>>>(pZf, pZs, 512 * EE, 0);
    split3<<<(nW + 255) / 256, 256>>>(Wv, pWvs, nW, 1);
    dim3 gOb(EE / 128, 512 / 128);
    gemm_mma_nt<<<gOb, 256, DSM_BYTES>>>(pZs, pWvs, bv, pObar, EE, K3, 0, 0, 0, 1.f);

    // 8) OutBar = Obar @ Wfc^T + bfc
    split3<<<(512 * EE + 255) / 256, 256>>>(pObar, pObars, 512 * EE, 0);
    split3<<<(nW + 255) / 256, 256>>>(Wfc, pWfcs, nW, 1);
    gemm_mma_nt<<<gOb, 256, DSM_BYTES>>>(pObars, pWfcs, bfc, pOutBar, EE, K3, 0, 0, 0, 1.f);

    // 9) final output
    final_kernel<<<RES_ELEMS / 256, 256>>>(x, pOutBar, out);
}

// round 8
// speedup vs baseline: 3.5573x; 1.1048x over previous
#include <cuda_runtime.h>
#include <cuda_bf16.h>
#include <math.h>
#include <stdint.h>

// Problem dims
#define TT 16
#define BB 32
#define NN 512
#define FF 128
#define EE 2048            // F*T
#define K3 6144            // 3*EE  (split-bf16 concatenated K)
#define MROWS 16384        // B*N
#define ATT_ELEMS (32*512*512)
#define RES_ELEMS (16*512*128)

// ---------------- device scratch (no allocations allowed) ----------------
__device__ float g_XR[(size_t)MROWS * EE];          // [B*N, E]
__device__ float g_Att[(size_t)ATT_ELEMS];
__device__ float g_Abar[(size_t)512 * 512];
__device__ float g_OutBar[(size_t)512 * EE];
__device__ float g_w2[EE];
__device__ float g_vvec[MROWS];

// bf16 split operands: A-mode rows = [hi | lo | hi], B-mode rows = [hi | hi | lo]
__device__ __nv_bfloat16 g_XRsA[(size_t)MROWS * K3];
__device__ __nv_bfloat16 g_XRsB[(size_t)MROWS * K3];
__device__ __nv_bfloat16 g_Ys  [(size_t)MROWS * K3];
__device__ __nv_bfloat16 g_M3s [(size_t)EE * K3];
__device__ __nv_bfloat16 g_WkTs[(size_t)EE * K3];
__device__ __nv_bfloat16 g_WqTs[(size_t)EE * K3];
__device__ __nv_bfloat16 g_Wvs [(size_t)EE * K3];
__device__ __nv_bfloat16 g_Wfcs[(size_t)EE * K3];
__device__ __nv_bfloat16 g_Zs  [(size_t)512 * K3];
__device__ __nv_bfloat16 g_Obars[(size_t)512 * K3];

// ================= helpers =================
__device__ __forceinline__ uint32_t smem_u32(const void* p) {
    uint32_t a;
    asm("{ .reg .u64 t; cvta.to.shared.u64 t, %1; cvt.u32.u64 %0, t; }" : "=r"(a) : "l"(p));
    return a;
}
#define SWZ128(off) ((off) ^ (((off) >> 3) & 0x70))

__device__ __forceinline__ void cp16(uint32_t s, const void* g) {
    asm volatile("cp.async.cg.shared.global [%0], [%1], 16;" :: "r"(s), "l"(g));
}
#define CP_COMMIT() asm volatile("cp.async.commit_group;" ::: "memory")
#define CP_WAIT1()  asm volatile("cp.async.wait_group 1;" ::: "memory")

__device__ __forceinline__ void ldmx4(uint32_t* f, uint32_t addr) {
    asm volatile("ldmatrix.sync.aligned.m8n8.x4.shared.b16 {%0,%1,%2,%3}, [%4];"
        : "=r"(f[0]), "=r"(f[1]), "=r"(f[2]), "=r"(f[3]) : "r"(addr));
}
__device__ __forceinline__ void mma16816(float* d, const uint32_t* a,
                                         uint32_t b0, uint32_t b1) {
    asm volatile("mma.sync.aligned.m16n8k16.row.col.f32.bf16.bf16.f32 "
        "{%0,%1,%2,%3}, {%4,%5,%6,%7}, {%8,%9}, {%0,%1,%2,%3};"
        : "+f"(d[0]), "+f"(d[1]), "+f"(d[2]), "+f"(d[3])
        : "r"(a[0]), "r"(a[1]), "r"(a[2]), "r"(a[3]), "r"(b0), "r"(b1));
}

__device__ __forceinline__ void store_split2(__nv_bfloat16* p, float x, float y, int emit) {
    __nv_bfloat162 h, l;
    h.x = __float2bfloat16(x); h.y = __float2bfloat16(y);
    l.x = __float2bfloat16(x - __bfloat162float(h.x));
    l.y = __float2bfloat16(y - __bfloat162float(h.y));
    *(__nv_bfloat162*)p = h;
    if (emit == 1) {   // A-mode [hi|lo|hi]
        *(__nv_bfloat162*)(p + 2048) = l;
        *(__nv_bfloat162*)(p + 4096) = h;
    } else {           // B-mode [hi|hi|lo]
        *(__nv_bfloat162*)(p + 2048) = h;
        *(__nv_bfloat162*)(p + 4096) = l;
    }
}

#define STAGE_BYTES 32768      // A 16KB + B 16KB (128 rows x 128B = 64 bf16 k-chunk)
#define NSTAGE 3
#define DSM_BYTES (NSTAGE * STAGE_BYTES + 128)

// ================= bf16 mma.sync NT GEMM =================
// C = scale*(A[M,K] @ B[N,K]^T) + bias. 128x128 tiles, BK=64 bf16, 3-stage cp.async.
// emit: 0 -> fp32 C [Ncols ld, batched by sC]; 1 -> split-A bf16 (ld=K3); 2 -> split-B.
__global__ void __launch_bounds__(256, 2)
gemm_mma_nt(const __nv_bfloat16* __restrict__ A, const __nv_bfloat16* __restrict__ B,
            const float* __restrict__ bias, void* __restrict__ Cv,
            int Ncols, int Kc, long long sA, long long sB, long long sC,
            float scale, int emit)
{
    extern __shared__ char sm[];
    A += (long long)blockIdx.z * sA;
    B += (long long)blockIdx.z * sB;

    const int tid = threadIdx.x, wid = tid >> 5, lane = tid & 31;
    const int row0 = blockIdx.y * 128, col0 = blockIdx.x * 128;
    const int wm = wid & 3, wn = wid >> 2;

    uint32_t sbase = (smem_u32(sm) + 127u) & ~127u;

    // loader mapping: row = tid>>1, 4 x 16B chunks starting at (tid&1)*4
    const int lrow = tid >> 1;
    const int lc0 = (tid & 1) * 4;
    const char* gA = (const char*)(A + (long long)(row0 + lrow) * Kc);
    const char* gB = (const char*)(B + (long long)(col0 + lrow) * Kc);
    uint32_t swo[4];
#pragma unroll
    for (int q = 0; q < 4; q++) {
        uint32_t off = (uint32_t)lrow * 128u + (lc0 + q) * 16u;
        swo[q] = SWZ128(off);
    }

    const int nc = Kc / 64;

    // prologue: chunks 0,1 -> stages 0,1
#pragma unroll
    for (int s = 0; s < 2; s++) {
        uint32_t aA = sbase + s * STAGE_BYTES;
        uint32_t aB = aA + 16384;
        long long kb = (long long)s * 128;
#pragma unroll
        for (int q = 0; q < 4; q++) {
            cp16(aA + swo[q], gA + kb + (lc0 + q) * 16);
            cp16(aB + swo[q], gB + kb + (lc0 + q) * 16);
        }
        CP_COMMIT();
    }

    float acc[2][8][4];
#pragma unroll
    for (int mi = 0; mi < 2; mi++)
#pragma unroll
        for (int ni = 0; ni < 8; ni++)
#pragma unroll
            for (int r = 0; r < 4; r++) acc[mi][ni][r] = 0.f;

    const int fr = lane & 15;
    const int fk = (lane >> 4) * 16;

    int st_c = 0;                 // stage holding chunk c
    int st_n = 2;                 // stage for chunk c+2
    for (int c = 0; c < nc; c++) {
        CP_WAIT1();               // chunk c resident
        __syncthreads();          // all warps done computing chunk c-1 (stage st_n)

        // prefetch chunk c+2 into stage st_n (freed by the sync above)
        if (c + 2 < nc) {
            uint32_t aA = sbase + st_n * STAGE_BYTES;
            uint32_t aB = aA + 16384;
            long long kb = (long long)(c + 2) * 128;
#pragma unroll
            for (int q = 0; q < 4; q++) {
                cp16(aA + swo[q], gA + kb + (lc0 + q) * 16);
                cp16(aB + swo[q], gB + kb + (lc0 + q) * 16);
            }
        }
        CP_COMMIT();

        // compute chunk c
        uint32_t aA = sbase + st_c * STAGE_BYTES;
        uint32_t aB = aA + 16384;
#pragma unroll
        for (int ks = 0; ks < 4; ks++) {
            const int kbyte = ks * 32 + fk;
            uint32_t af[2][4];
#pragma unroll
            for (int mi = 0; mi < 2; mi++) {
                int r = wm * 32 + mi * 16 + fr;
                ldmx4(af[mi], aA + SWZ128((uint32_t)(r * 128 + kbyte)));
            }
#pragma unroll
            for (int bi = 0; bi < 4; bi++) {
                uint32_t bf[4];
                int r = wn * 64 + bi * 16 + fr;
                ldmx4(bf, aB + SWZ128((uint32_t)(r * 128 + kbyte)));
#pragma unroll
                for (int mi = 0; mi < 2; mi++) {
                    mma16816(acc[mi][2 * bi + 0], af[mi], bf[0], bf[2]);
                    mma16816(acc[mi][2 * bi + 1], af[mi], bf[1], bf[3]);
                }
            }
        }
        st_c = (st_c == 2) ? 0 : st_c + 1;
        st_n = (st_n == 2) ? 0 : st_n + 1;
    }

    // epilogue
    if (emit == 0) {
        float* C = (float*)Cv + (long long)blockIdx.z * sC;
#pragma unroll
        for (int mi = 0; mi < 2; mi++) {
            int r = row0 + wm * 32 + mi * 16 + (lane >> 2);
#pragma unroll
            for (int ni = 0; ni < 8; ni++) {
                int cc = col0 + wn * 64 + ni * 8 + (lane & 3) * 2;
                float b0 = bias ? bias[cc] : 0.f;
                float b1 = bias ? bias[cc + 1] : 0.f;
                float2 v0, v1;
                v0.x = acc[mi][ni][0] * scale + b0;
                v0.y = acc[mi][ni][1] * scale + b1;
                v1.x = acc[mi][ni][2] * scale + b0;
                v1.y = acc[mi][ni][3] * scale + b1;
                *(float2*)(C + (long long)r * Ncols + cc) = v0;
                *(float2*)(C + (long long)(r + 8) * Ncols + cc) = v1;
            }
        }
    } else {
        __nv_bfloat16* C = (__nv_bfloat16*)Cv;
#pragma unroll
        for (int mi = 0; mi < 2; mi++) {
            int r = row0 + wm * 32 + mi * 16 + (lane >> 2);
#pragma unroll
            for (int ni = 0; ni < 8; ni++) {
                int cc = col0 + wn * 64 + ni * 8 + (lane & 3) * 2;
                float b0 = bias ? bias[cc] : 0.f;
                float b1 = bias ? bias[cc + 1] : 0.f;
                store_split2(C + (long long)r * K3 + cc,
                             acc[mi][ni][0] * scale + b0,
                             acc[mi][ni][1] * scale + b1, emit);
                store_split2(C + (long long)(r + 8) * K3 + cc,
                             acc[mi][ni][2] * scale + b0,
                             acc[mi][ni][3] * scale + b1, emit);
            }
        }
    }
}

// ================= elementwise kernels =================
// X fp32 [R,2048] -> Y bf16 [R,6144]
__global__ void __launch_bounds__(256) split3(const float* __restrict__ X,
                                              __nv_bfloat16* __restrict__ Y,
                                              int n, int modeB) {
    int i = blockIdx.x * 256 + threadIdx.x;
    if (i >= n) return;
    int r = i >> 11, k = i & 2047;
    float x = X[i];
    __nv_bfloat16 h = __float2bfloat16(x);
    __nv_bfloat16 l = __float2bfloat16(x - __bfloat162float(h));
    __nv_bfloat16* yr = Y + (size_t)r * K3;
    yr[k] = h;
    yr[2048 + k] = modeB ? h : l;
    yr[4096 + k] = modeB ? l : h;
}

// transpose + split: Y[r, k] = W[k, r]
__global__ void __launch_bounds__(256) split3t(const float* __restrict__ W,
                                               __nv_bfloat16* __restrict__ Y, int modeB) {
    __shared__ float t[32][33];
    int tx = threadIdx.x & 31, ty = threadIdx.x >> 5;
    int cbase = blockIdx.x * 32;
    int rbase = blockIdx.y * 32;
#pragma unroll
    for (int j = 0; j < 4; j++)
        t[ty + j * 8][tx] = W[(size_t)(rbase + ty + j * 8) * EE + cbase + tx];
    __syncthreads();
#pragma unroll
    for (int j = 0; j < 4; j++) {
        int r = cbase + ty + j * 8;
        int k = rbase + tx;
        float x = t[tx][ty + j * 8];
        __nv_bfloat16 h = __float2bfloat16(x);
        __nv_bfloat16 l = __float2bfloat16(x - __bfloat162float(h));
        __nv_bfloat16* yr = Y + (size_t)r * K3;
        yr[k] = h;
        yr[2048 + k] = modeB ? h : l;
        yr[4096 + k] = modeB ? l : h;
    }
}

// build XR + both split forms in one pass
__global__ void __launch_bounds__(256) build_xr_split(const float* __restrict__ x,
                                                      float* __restrict__ xr,
                                                      __nv_bfloat16* __restrict__ xrA,
                                                      __nv_bfloat16* __restrict__ xrB) {
    __shared__ float s[TT * 129];
    int bn = blockIdx.x;
    int b = bn >> 9, n = bn & 511;
    for (int i = threadIdx.x; i < TT * FF; i += 256) {
        int t = i >> 7, f = i & 127;
        s[t * 129 + f] = x[((size_t)(t * BB + b) * NN + n) * FF + f];
    }
    __syncthreads();
    for (int e = threadIdx.x; e < EE; e += 256) {
        int t = e & 15, f = e >> 4;
        float v = s[t * 129 + f];
        xr[(size_t)bn * EE + e] = v;
        __nv_bfloat16 h = __float2bfloat16(v);
        __nv_bfloat16 l = __float2bfloat16(v - __bfloat162float(h));
        size_t rb = (size_t)bn * K3 + e;
        xrA[rb] = h; xrA[rb + 2048] = l; xrA[rb + 4096] = h;
        xrB[rb] = h; xrB[rb + 2048] = h; xrB[rb + 4096] = l;
    }
}

// w2 = Wk^T bq ; v = scale * XR @ w2
__global__ void __launch_bounds__(256) wkbq_kernel(const float* __restrict__ Wk,
                                                   const float* __restrict__ bq,
                                                   float* __restrict__ w2) {
    int e = blockIdx.x * 256 + threadIdx.x;
    float s = 0.f;
    for (int d = 0; d < EE; d++) s += Wk[(size_t)d * EE + e] * bq[d];
    w2[e] = s;
}
__global__ void __launch_bounds__(256) xrw2_kernel(const float* __restrict__ XR,
                                                   const float* __restrict__ w2,
                                                   float* __restrict__ v, float scale) {
    int g = blockIdx.x * 8 + (threadIdx.x >> 5);
    int lane = threadIdx.x & 31;
    const float* r = XR + (size_t)g * EE;
    float s = 0.f;
    for (int e = lane; e < EE; e += 32) s += r[e] * w2[e];
#pragma unroll
    for (int o = 16; o; o >>= 1) s += __shfl_xor_sync(0xffffffffu, s, o);
    if (lane == 0) v[g] = s * scale;
}

// row softmax with additive per-column vector
__global__ void __launch_bounds__(128) softmax_rows(float* __restrict__ att,
                                                    const float* __restrict__ vadd) {
    size_t row = blockIdx.x;
    int b = (int)(row >> 9);
    float4* p = (float4*)(att + row * 512);
    const float4* vv = (const float4*)(vadd + (size_t)b * 512);
    float4 v = p[threadIdx.x];
    float4 a = vv[threadIdx.x];
    v.x += a.x; v.y += a.y; v.z += a.z; v.w += a.w;
    float m = fmaxf(fmaxf(v.x, v.y), fmaxf(v.z, v.w));
#pragma unroll
    for (int o = 16; o; o >>= 1) m = fmaxf(m, __shfl_xor_sync(0xffffffffu, m, o));
    __shared__ float sm[4];
    if ((threadIdx.x & 31) == 0) sm[threadIdx.x >> 5] = m;
    __syncthreads();
    m = fmaxf(fmaxf(sm[0], sm[1]), fmaxf(sm[2], sm[3]));
    v.x = __expf(v.x - m); v.y = __expf(v.y - m);
    v.z = __expf(v.z - m); v.w = __expf(v.w - m);
    float s = v.x + v.y + v.z + v.w;
#pragma unroll
    for (int o = 16; o; o >>= 1) s += __shfl_xor_sync(0xffffffffu, s, o);
    __shared__ float ss[4];
    if ((threadIdx.x & 31) == 0) ss[threadIdx.x >> 5] = s;
    __syncthreads();
    s = ss[0] + ss[1] + ss[2] + ss[3];
    float inv = 1.f / s;
    v.x *= inv; v.y *= inv; v.z *= inv; v.w *= inv;
    p[threadIdx.x] = v;
}

// Abar
__global__ void __launch_bounds__(512) abar_kernel(const float* __restrict__ att,
                                                   float* __restrict__ abar) {
    int bg = blockIdx.x;
    int b = bg >> 4, g = bg & 15;
    const float* bse = att + ((size_t)b * 512 + g * 32) * 512;
    int j = threadIdx.x;
    float s = 0.f;
#pragma unroll 8
    for (int r = 0; r < 32; r++) s += bse[(size_t)r * 512 + j];
    abar[(size_t)bg * 512 + j] = s * (1.f / 32.f);
}

// Z = Abar_b @ XR_b, emitted directly as split-A bf16
__global__ void __launch_bounds__(128) zbar_split(const float* __restrict__ abar,
                                                  const float* __restrict__ XR,
                                                  __nv_bfloat16* __restrict__ Zs) {
    int b = blockIdx.y;
    int col0 = blockIdx.x * 128;
    __shared__ float sA[16 * 512];
    for (int i = threadIdx.x; i < 16 * 512; i += 128)
        sA[i] = abar[(size_t)b * 16 * 512 + i];
    __syncthreads();
    float acc[16];
#pragma unroll
    for (int g = 0; g < 16; g++) acc[g] = 0.f;
    const float* vb = XR + (size_t)b * 512 * EE + col0 + threadIdx.x;
    for (int l = 0; l < 512; l++) {
        float vv = vb[(size_t)l * EE];
#pragma unroll
        for (int g = 0; g < 16; g++) acc[g] = fmaf(sA[g * 512 + l], vv, acc[g]);
    }
#pragma unroll
    for (int g = 0; g < 16; g++) {
        float v = acc[g];
        __nv_bfloat16 h = __float2bfloat16(v);
        __nv_bfloat16 l2 = __float2bfloat16(v - __bfloat162float(h));
        size_t rb = ((size_t)b * 16 + g) * K3 + col0 + threadIdx.x;
        Zs[rb] = h; Zs[rb + 2048] = l2; Zs[rb + 4096] = h;
    }
}

// final
__global__ void __launch_bounds__(256) final_kernel(const float* __restrict__ x,
                                                    const float* __restrict__ outbar,
                                                    float* __restrict__ out) {
    int idx = blockIdx.x * 256 + threadIdx.x;
    int f = idx & 127;
    int i = (idx >> 7) & 511;
    int t = idx >> 16;
    const float* px = x + (size_t)t * (BB * NN * FF) + (size_t)i * FF + f;
    float s = 0.f;
#pragma unroll 8
    for (int b = 0; b < 32; b++) s += px[(size_t)b * (NN * FF)];
    out[idx] = s * (1.f / 32.f) + outbar[(size_t)i * EE + t * FF + f];
}

// ---------------- launcher ----------------
extern "C" void kernel_launch(void* const* d_in, const int* in_sizes, int n_in,
                              void* d_out, int out_size) {
    const float* x   = (const float*)d_in[0];
    const float* Wq  = (const float*)d_in[1];
    const float* bq  = (const float*)d_in[2];
    const float* Wk  = (const float*)d_in[3];
    const float* Wv  = (const float*)d_in[5];
    const float* bv  = (const float*)d_in[6];
    const float* Wfc = (const float*)d_in[7];
    const float* bfc = (const float*)d_in[8];
    float* out = (float*)d_out;

    float *pXR, *pAtt, *pAbar, *pOutBar, *pw2, *pv;
    __nv_bfloat16 *pXRsA, *pXRsB, *pYs, *pM3s, *pWkTs, *pWqTs, *pWvs, *pWfcs, *pZs, *pObars;
    cudaGetSymbolAddress((void**)&pXR, g_XR);
    cudaGetSymbolAddress((void**)&pAbar, g_Abar);
    cudaGetSymbolAddress((void**)&pOutBar, g_OutBar);
    cudaGetSymbolAddress((void**)&pw2, g_w2);
    cudaGetSymbolAddress((void**)&pv, g_vvec);
    cudaGetSymbolAddress((void**)&pXRsA, g_XRsA);
    cudaGetSymbolAddress((void**)&pXRsB, g_XRsB);
    cudaGetSymbolAddress((void**)&pYs, g_Ys);
    cudaGetSymbolAddress((void**)&pM3s, g_M3s);
    cudaGetSymbolAddress((void**)&pWkTs, g_WkTs);
    cudaGetSymbolAddress((void**)&pWqTs, g_WqTs);
    cudaGetSymbolAddress((void**)&pWvs, g_Wvs);
    cudaGetSymbolAddress((void**)&pWfcs, g_Wfcs);
    cudaGetSymbolAddress((void**)&pZs, g_Zs);
    cudaGetSymbolAddress((void**)&pObars, g_Obars);

    if (out_size >= RES_ELEMS + ATT_ELEMS) pAtt = out + RES_ELEMS;
    else cudaGetSymbolAddress((void**)&pAtt, g_Att);

    cudaFuncSetAttribute(gemm_mma_nt, cudaFuncAttributeMaxDynamicSharedMemorySize, DSM_BYTES);

    const float scale = rsqrtf((float)EE);
    const int nW = EE * EE;

    // 1) XR + its splits (single pass over x)
    build_xr_split<<<MROWS, 256>>>(x, pXR, pXRsA, pXRsB);

    // 2) M3 = Wk^T Wq  -> emit split-B directly
    dim3 gT(64, 64);
    split3t<<<gT, 256>>>(Wk, pWkTs, 0);
    split3t<<<gT, 256>>>(Wq, pWqTs, 1);
    dim3 gM3(EE / 128, EE / 128);
    gemm_mma_nt<<<gM3, 256, DSM_BYTES>>>(pWkTs, pWqTs, nullptr, pM3s, 0, K3, 0, 0, 0, 1.f, 2);

    // 3) Y = XR @ M3^T -> emit split-A directly
    dim3 gY(EE / 128, MROWS / 128);
    gemm_mma_nt<<<gY, 256, DSM_BYTES>>>(pXRsA, pM3s, nullptr, pYs, 0, K3, 0, 0, 0, 1.f, 1);

    // 4) energy core = scale * Y_b XR_b^T  (batched over 32) -> fp32 att
    dim3 gE(512 / 128, 512 / 128, 32);
    gemm_mma_nt<<<gE, 256, DSM_BYTES>>>(pYs, pXRsB, nullptr, pAtt, 512, K3,
                                        (long long)512 * K3, (long long)512 * K3,
                                        (long long)512 * 512, scale, 0);

    // 5) bias column vector; softmax with +v[j]
    wkbq_kernel<<<EE / 256, 256>>>(Wk, bq, pw2);
    xrw2_kernel<<<MROWS / 8, 256>>>(pXR, pw2, pv, scale);
    softmax_rows<<<32 * 512, 128>>>(pAtt, pv);

    // 6) Abar, Z = Abar @ XR (split-A emitted)
    abar_kernel<<<512, 512>>>(pAtt, pAbar);
    dim3 gZ(EE / 128, 32);
    zbar_split<<<gZ, 128>>>(pAbar, pXR, pZs);

    // 7) Obar = Z @ Wv^T + bv -> emit split-A
    split3<<<(nW + 255) / 256, 256>>>(Wv, pWvs, nW, 1);
    dim3 gOb(EE / 128, 512 / 128);
    gemm_mma_nt<<<gOb, 256, DSM_BYTES>>>(pZs, pWvs, bv, pObars, 0, K3, 0, 0, 0, 1.f, 1);

    // 8) OutBar = Obar @ Wfc^T + bfc -> fp32
    split3<<<(nW + 255) / 256, 256>>>(Wfc, pWfcs, nW, 1);
    gemm_mma_nt<<<gOb, 256, DSM_BYTES>>>(pObars, pWfcs, bfc, pOutBar, EE, K3, 0, 0, 0, 1.f, 0);

    // 9) final output
    final_kernel<<<RES_ELEMS / 256, 256>>>(x, pOutBar, out);
}

// round 9
// speedup vs baseline: 3.6658x; 1.0305x over previous
#include <cuda_runtime.h>
#include <cuda_bf16.h>
#include <math.h>
#include <stdint.h>

// Problem dims
#define TT 16
#define BB 32
#define NN 512
#define FF 128
#define EE 2048            // F*T
#define K2 4096            // canonical split storage: [hi(2048) | lo(2048)]
#define NC 96              // K3=6144 virtual -> 96 chunks of 64 bf16
#define MROWS 16384        // B*N
#define ATT_ELEMS (32*512*512)
#define RES_ELEMS (16*512*128)

// ---------------- device scratch ----------------
__device__ float g_XR[(size_t)MROWS * EE];
__device__ float g_Att[(size_t)ATT_ELEMS];
__device__ float g_Abar[(size_t)512 * 512];
__device__ float g_OutBar[(size_t)512 * EE];
__device__ float g_w2[EE];
__device__ float g_vvec[MROWS];

// canonical split-bf16 buffers: row = [hi | lo], 4096 elems
__device__ __nv_bfloat16 g_XRs[(size_t)MROWS * K2];
__device__ __nv_bfloat16 g_Ys [(size_t)MROWS * K2];
__device__ __nv_bfloat16 g_M3s[(size_t)EE * K2];
__device__ __nv_bfloat16 g_WkTs[(size_t)EE * K2];
__device__ __nv_bfloat16 g_WqTs[(size_t)EE * K2];
__device__ __nv_bfloat16 g_Wvs [(size_t)EE * K2];
__device__ __nv_bfloat16 g_Wfcs[(size_t)EE * K2];
__device__ __nv_bfloat16 g_Zs  [(size_t)512 * K2];
__device__ __nv_bfloat16 g_Obars[(size_t)512 * K2];

// ================= helpers =================
__device__ __forceinline__ uint32_t smem_u32(const void* p) {
    uint32_t a;
    asm("{ .reg .u64 t; cvta.to.shared.u64 t, %1; cvt.u32.u64 %0, t; }" : "=r"(a) : "l"(p));
    return a;
}
#define SWZ128(off) ((off) ^ (((off) >> 3) & 0x70))

__device__ __forceinline__ void cp16(uint32_t s, const void* g) {
    asm volatile("cp.async.cg.shared.global [%0], [%1], 16;" :: "r"(s), "l"(g));
}
#define CP_COMMIT() asm volatile("cp.async.commit_group;" ::: "memory")
#define CP_WAIT1()  asm volatile("cp.async.wait_group 1;" ::: "memory")

__device__ __forceinline__ void ldmx4(uint32_t* f, uint32_t addr) {
    asm volatile("ldmatrix.sync.aligned.m8n8.x4.shared.b16 {%0,%1,%2,%3}, [%4];"
        : "=r"(f[0]), "=r"(f[1]), "=r"(f[2]), "=r"(f[3]) : "r"(addr));
}
__device__ __forceinline__ void mma16816(float* d, const uint32_t* a,
                                         uint32_t b0, uint32_t b1) {
    asm volatile("mma.sync.aligned.m16n8k16.row.col.f32.bf16.bf16.f32 "
        "{%0,%1,%2,%3}, {%4,%5,%6,%7}, {%8,%9}, {%0,%1,%2,%3};"
        : "+f"(d[0]), "+f"(d[1]), "+f"(d[2]), "+f"(d[3])
        : "r"(a[0]), "r"(a[1]), "r"(a[2]), "r"(a[3]), "r"(b0), "r"(b1));
}

// canonical split store: hi at p, lo at p+2048
__device__ __forceinline__ void store_split2(__nv_bfloat16* p, float x, float y) {
    __nv_bfloat162 h, l;
    h.x = __float2bfloat16(x); h.y = __float2bfloat16(y);
    l.x = __float2bfloat16(x - __bfloat162float(h.x));
    l.y = __float2bfloat16(y - __bfloat162float(h.y));
    *(__nv_bfloat162*)p = h;
    *(__nv_bfloat162*)(p + 2048) = l;
}

// chunk -> byte offset within canonical [hi|lo] row (8192 bytes)
// A operand pattern [H,L,H]; B operand pattern [H,H,L]
__device__ __forceinline__ int offA_of(int c) { return ((c < 64) ? c : c - 64) * 128; }
__device__ __forceinline__ int offB_of(int c) { return ((c < 32) ? c : c - 32) * 128; }

#define STAGE_BYTES 32768      // A 16KB + B 16KB (128 rows x 128B = 64 bf16 k-chunk)
#define NSTAGE 3
#define DSM_BYTES (NSTAGE * STAGE_BYTES + 128)

// ================= bf16 mma.sync NT GEMM (3-term split via chunk remap) ===========
// C = scale*(A3 @ B3^T) + bias where A3/B3 are the virtual K3=6144 split operands
// stored canonically as [R, 4096]. 128x128 tiles, 96 chunks, 3-stage cp.async ring.
// emit: 0 -> fp32 C [Ncols, batched by sC]; 1 -> canonical split bf16 (ld=K2).
__global__ void __launch_bounds__(256, 2)
gemm_mma_nt(const __nv_bfloat16* __restrict__ A, const __nv_bfloat16* __restrict__ B,
            const float* __restrict__ bias, void* __restrict__ Cv,
            int Ncols, long long sA, long long sB, long long sC,
            float scale, int emit)
{
    extern __shared__ char sm[];
    A += (long long)blockIdx.z * sA;
    B += (long long)blockIdx.z * sB;

    const int tid = threadIdx.x, wid = tid >> 5, lane = tid & 31;
    const int row0 = blockIdx.y * 128, col0 = blockIdx.x * 128;
    const int wm = wid & 3, wn = wid >> 2;

    uint32_t sbase = (smem_u32(sm) + 127u) & ~127u;

    // loader mapping: row = tid>>1, 4 x 16B chunks starting at (tid&1)*4
    const int lrow = tid >> 1;
    const int lc0 = (tid & 1) * 4;
    const char* gA = (const char*)(A + (long long)(row0 + lrow) * K2);
    const char* gB = (const char*)(B + (long long)(col0 + lrow) * K2);
    uint32_t swo[4];
#pragma unroll
    for (int q = 0; q < 4; q++) {
        uint32_t off = (uint32_t)lrow * 128u + (lc0 + q) * 16u;
        swo[q] = SWZ128(off);
    }

    // prologue: chunks 0,1 -> stages 0,1  (offA=offB=c*128 for c<32)
#pragma unroll
    for (int s = 0; s < 2; s++) {
        uint32_t aA = sbase + s * STAGE_BYTES;
        uint32_t aB = aA + 16384;
        int kb = s * 128;
#pragma unroll
        for (int q = 0; q < 4; q++) {
            cp16(aA + swo[q], gA + kb + (lc0 + q) * 16);
            cp16(aB + swo[q], gB + kb + (lc0 + q) * 16);
        }
        CP_COMMIT();
    }

    float acc[2][8][4];
#pragma unroll
    for (int mi = 0; mi < 2; mi++)
#pragma unroll
        for (int ni = 0; ni < 8; ni++)
#pragma unroll
            for (int r = 0; r < 4; r++) acc[mi][ni][r] = 0.f;

    const int fr = lane & 15;
    const int fk = (lane >> 4) * 16;
    // hoisted fragment row byte offsets
    uint32_t arow[2], brow[4];
#pragma unroll
    for (int mi = 0; mi < 2; mi++) arow[mi] = (uint32_t)(wm * 32 + mi * 16 + fr) * 128u;
#pragma unroll
    for (int bi = 0; bi < 4; bi++) brow[bi] = (uint32_t)(wn * 64 + bi * 16 + fr) * 128u;

    int st_c = 0, st_n = 2;
    for (int c = 0; c < NC; c++) {
        CP_WAIT1();               // chunk c resident
        __syncthreads();          // chunk c-1 consumed by all warps (stage st_n free)

        if (c + 2 < NC) {
            uint32_t aA = sbase + st_n * STAGE_BYTES;
            uint32_t aB = aA + 16384;
            int oA = offA_of(c + 2), oB = offB_of(c + 2);
#pragma unroll
            for (int q = 0; q < 4; q++) {
                cp16(aA + swo[q], gA + oA + (lc0 + q) * 16);
                cp16(aB + swo[q], gB + oB + (lc0 + q) * 16);
            }
        }
        CP_COMMIT();

        // compute chunk c, fragment-pipelined
        uint32_t aA = sbase + st_c * STAGE_BYTES;
        uint32_t aB = aA + 16384;
        uint32_t af[2][2][4];   // [ks&1][mi][4]
        uint32_t bf[2][4];      // [bi&1][4]
        // preload ks=0 A frags and (ks=0,bi=0) B frag
#pragma unroll
        for (int mi = 0; mi < 2; mi++)
            ldmx4(af[0][mi], aA + SWZ128(arow[mi] + fk));
        ldmx4(bf[0], aB + SWZ128(brow[0] + fk));

#pragma unroll
        for (int ks = 0; ks < 4; ks++) {
            const int cur = ks & 1;
            if (ks < 3) {
                const int kb2 = (ks + 1) * 32 + fk;
#pragma unroll
                for (int mi = 0; mi < 2; mi++)
                    ldmx4(af[cur ^ 1][mi], aA + SWZ128(arow[mi] + kb2));
            }
            const int kbyte = ks * 32 + fk;
#pragma unroll
            for (int bi = 0; bi < 4; bi++) {
                const int bcur = bi & 1;
                if (bi < 3)
                    ldmx4(bf[bcur ^ 1], aB + SWZ128(brow[bi + 1] + kbyte));
                else if (ks < 3)
                    ldmx4(bf[bcur ^ 1], aB + SWZ128(brow[0] + (ks + 1) * 32 + fk));
#pragma unroll
                for (int mi = 0; mi < 2; mi++) {
                    mma16816(acc[mi][2 * bi + 0], af[cur][mi], bf[bcur][0], bf[bcur][2]);
                    mma16816(acc[mi][2 * bi + 1], af[cur][mi], bf[bcur][1], bf[bcur][3]);
                }
            }
        }
        st_c = (st_c == 2) ? 0 : st_c + 1;
        st_n = (st_n == 2) ? 0 : st_n + 1;
    }

    // epilogue
    if (emit == 0) {
        float* C = (float*)Cv + (long long)blockIdx.z * sC;
#pragma unroll
        for (int mi = 0; mi < 2; mi++) {
            int r = row0 + wm * 32 + mi * 16 + (lane >> 2);
#pragma unroll
            for (int ni = 0; ni < 8; ni++) {
                int cc = col0 + wn * 64 + ni * 8 + (lane & 3) * 2;
                float b0 = bias ? bias[cc] : 0.f;
                float b1 = bias ? bias[cc + 1] : 0.f;
                float2 v0, v1;
                v0.x = acc[mi][ni][0] * scale + b0;
                v0.y = acc[mi][ni][1] * scale + b1;
                v1.x = acc[mi][ni][2] * scale + b0;
                v1.y = acc[mi][ni][3] * scale + b1;
                *(float2*)(C + (long long)r * Ncols + cc) = v0;
                *(float2*)(C + (long long)(r + 8) * Ncols + cc) = v1;
            }
        }
    } else {
        __nv_bfloat16* C = (__nv_bfloat16*)Cv;
#pragma unroll
        for (int mi = 0; mi < 2; mi++) {
            int r = row0 + wm * 32 + mi * 16 + (lane >> 2);
#pragma unroll
            for (int ni = 0; ni < 8; ni++) {
                int cc = col0 + wn * 64 + ni * 8 + (lane & 3) * 2;
                float b0 = bias ? bias[cc] : 0.f;
                float b1 = bias ? bias[cc + 1] : 0.f;
                store_split2(C + (long long)r * K2 + cc,
                             acc[mi][ni][0] * scale + b0,
                             acc[mi][ni][1] * scale + b1);
                store_split2(C + (long long)(r + 8) * K2 + cc,
                             acc[mi][ni][2] * scale + b0,
                             acc[mi][ni][3] * scale + b1);
            }
        }
    }
}

// ================= elementwise kernels =================
// X fp32 [R,2048] -> canonical split [R,4096]
__global__ void __launch_bounds__(256) split3(const float* __restrict__ X,
                                              __nv_bfloat16* __restrict__ Y, int n) {
    int i = blockIdx.x * 256 + threadIdx.x;
    if (i >= n) return;
    int r = i >> 11, k = i & 2047;
    float x = X[i];
    __nv_bfloat16 h = __float2bfloat16(x);
    __nv_bfloat16 l = __float2bfloat16(x - __bfloat162float(h));
    __nv_bfloat16* yr = Y + (size_t)r * K2;
    yr[k] = h;
    yr[2048 + k] = l;
}

// transpose + canonical split: Y[r, k] = W[k, r]
__global__ void __launch_bounds__(256) split3t(const float* __restrict__ W,
                                               __nv_bfloat16* __restrict__ Y) {
    __shared__ float t[32][33];
    int tx = threadIdx.x & 31, ty = threadIdx.x >> 5;
    int cbase = blockIdx.x * 32;
    int rbase = blockIdx.y * 32;
#pragma unroll
    for (int j = 0; j < 4; j++)
        t[ty + j * 8][tx] = W[(size_t)(rbase + ty + j * 8) * EE + cbase + tx];
    __syncthreads();
#pragma unroll
    for (int j = 0; j < 4; j++) {
        int r = cbase + ty + j * 8;
        int k = rbase + tx;
        float x = t[tx][ty + j * 8];
        __nv_bfloat16 h = __float2bfloat16(x);
        __nv_bfloat16 l = __float2bfloat16(x - __bfloat162float(h));
        __nv_bfloat16* yr = Y + (size_t)r * K2;
        yr[k] = h;
        yr[2048 + k] = l;
    }
}

// build XR + canonical split in one pass
__global__ void __launch_bounds__(256) build_xr_split(const float* __restrict__ x,
                                                      float* __restrict__ xr,
                                                      __nv_bfloat16* __restrict__ xrs) {
    __shared__ float s[TT * 129];
    int bn = blockIdx.x;
    int b = bn >> 9, n = bn & 511;
    for (int i = threadIdx.x; i < TT * FF; i += 256) {
        int t = i >> 7, f = i & 127;
        s[t * 129 + f] = x[((size_t)(t * BB + b) * NN + n) * FF + f];
    }
    __syncthreads();
    for (int e = threadIdx.x; e < EE; e += 256) {
        int t = e & 15, f = e >> 4;
        float v = s[t * 129 + f];
        xr[(size_t)bn * EE + e] = v;
        __nv_bfloat16 h = __float2bfloat16(v);
        __nv_bfloat16 l = __float2bfloat16(v - __bfloat162float(h));
        size_t rb = (size_t)bn * K2 + e;
        xrs[rb] = h;
        xrs[rb + 2048] = l;
    }
}

// w2 = Wk^T bq ; v = scale * XR @ w2
__global__ void __launch_bounds__(256) wkbq_kernel(const float* __restrict__ Wk,
                                                   const float* __restrict__ bq,
                                                   float* __restrict__ w2) {
    int e = blockIdx.x * 256 + threadIdx.x;
    float s = 0.f;
    for (int d = 0; d < EE; d++) s += Wk[(size_t)d * EE + e] * bq[d];
    w2[e] = s;
}
__global__ void __launch_bounds__(256) xrw2_kernel(const float* __restrict__ XR,
                                                   const float* __restrict__ w2,
                                                   float* __restrict__ v, float scale) {
    int g = blockIdx.x * 8 + (threadIdx.x >> 5);
    int lane = threadIdx.x & 31;
    const float* r = XR + (size_t)g * EE;
    float s = 0.f;
    for (int e = lane; e < EE; e += 32) s += r[e] * w2[e];
#pragma unroll
    for (int o = 16; o; o >>= 1) s += __shfl_xor_sync(0xffffffffu, s, o);
    if (lane == 0) v[g] = s * scale;
}

// row softmax with additive per-column vector
__global__ void __launch_bounds__(128) softmax_rows(float* __restrict__ att,
                                                    const float* __restrict__ vadd) {
    size_t row = blockIdx.x;
    int b = (int)(row >> 9);
    float4* p = (float4*)(att + row * 512);
    const float4* vv = (const float4*)(vadd + (size_t)b * 512);
    float4 v = p[threadIdx.x];
    float4 a = vv[threadIdx.x];
    v.x += a.x; v.y += a.y; v.z += a.z; v.w += a.w;
    float m = fmaxf(fmaxf(v.x, v.y), fmaxf(v.z, v.w));
#pragma unroll
    for (int o = 16; o; o >>= 1) m = fmaxf(m, __shfl_xor_sync(0xffffffffu, m, o));
    __shared__ float sm[4];
    if ((threadIdx.x & 31) == 0) sm[threadIdx.x >> 5] = m;
    __syncthreads();
    m = fmaxf(fmaxf(sm[0], sm[1]), fmaxf(sm[2], sm[3]));
    v.x = __expf(v.x - m); v.y = __expf(v.y - m);
    v.z = __expf(v.z - m); v.w = __expf(v.w - m);
    float s = v.x + v.y + v.z + v.w;
#pragma unroll
    for (int o = 16; o; o >>= 1) s += __shfl_xor_sync(0xffffffffu, s, o);
    __shared__ float ss[4];
    if ((threadIdx.x & 31) == 0) ss[threadIdx.x >> 5] = s;
    __syncthreads();
    s = ss[0] + ss[1] + ss[2] + ss[3];
    float inv = 1.f / s;
    v.x *= inv; v.y *= inv; v.z *= inv; v.w *= inv;
    p[threadIdx.x] = v;
}

// Abar
__global__ void __launch_bounds__(512) abar_kernel(const float* __restrict__ att,
                                                   float* __restrict__ abar) {
    int bg = blockIdx.x;
    int b = bg >> 4, g = bg & 15;
    const float* bse = att + ((size_t)b * 512 + g * 32) * 512;
    int j = threadIdx.x;
    float s = 0.f;
#pragma unroll 8
    for (int r = 0; r < 32; r++) s += bse[(size_t)r * 512 + j];
    abar[(size_t)bg * 512 + j] = s * (1.f / 32.f);
}

// Z = Abar_b @ XR_b, emitted canonical split
__global__ void __launch_bounds__(128) zbar_split(const float* __restrict__ abar,
                                                  const float* __restrict__ XR,
                                                  __nv_bfloat16* __restrict__ Zs) {
    int b = blockIdx.y;
    int col0 = blockIdx.x * 128;
    __shared__ float sA[16 * 512];
    for (int i = threadIdx.x; i < 16 * 512; i += 128)
        sA[i] = abar[(size_t)b * 16 * 512 + i];
    __syncthreads();
    float acc[16];
#pragma unroll
    for (int g = 0; g < 16; g++) acc[g] = 0.f;
    const float* vb = XR + (size_t)b * 512 * EE + col0 + threadIdx.x;
    for (int l = 0; l < 512; l++) {
        float vv = vb[(size_t)l * EE];
#pragma unroll
        for (int g = 0; g < 16; g++) acc[g] = fmaf(sA[g * 512 + l], vv, acc[g]);
    }
#pragma unroll
    for (int g = 0; g < 16; g++) {
        float v = acc[g];
        __nv_bfloat16 h = __float2bfloat16(v);
        __nv_bfloat16 l2 = __float2bfloat16(v - __bfloat162float(h));
        size_t rb = ((size_t)b * 16 + g) * K2 + col0 + threadIdx.x;
        Zs[rb] = h;
        Zs[rb + 2048] = l2;
    }
}

// final
__global__ void __launch_bounds__(256) final_kernel(const float* __restrict__ x,
                                                    const float* __restrict__ outbar,
                                                    float* __restrict__ out) {
    int idx = blockIdx.x * 256 + threadIdx.x;
    int f = idx & 127;
    int i = (idx >> 7) & 511;
    int t = idx >> 16;
    const float* px = x + (size_t)t * (BB * NN * FF) + (size_t)i * FF + f;
    float s = 0.f;
#pragma unroll 8
    for (int b = 0; b < 32; b++) s += px[(size_t)b * (NN * FF)];
    out[idx] = s * (1.f / 32.f) + outbar[(size_t)i * EE + t * FF + f];
}

// ---------------- launcher ----------------
extern "C" void kernel_launch(void* const* d_in, const int* in_sizes, int n_in,
                              void* d_out, int out_size) {
    const float* x   = (const float*)d_in[0];
    const float* Wq  = (const float*)d_in[1];
    const float* bq  = (const float*)d_in[2];
    const float* Wk  = (const float*)d_in[3];
    const float* Wv  = (const float*)d_in[5];
    const float* bv  = (const float*)d_in[6];
    const float* Wfc = (const float*)d_in[7];
    const float* bfc = (const float*)d_in[8];
    float* out = (float*)d_out;

    float *pXR, *pAtt, *pAbar, *pOutBar, *pw2, *pv;
    __nv_bfloat16 *pXRs, *pYs, *pM3s, *pWkTs, *pWqTs, *pWvs, *pWfcs, *pZs, *pObars;
    cudaGetSymbolAddress((void**)&pXR, g_XR);
    cudaGetSymbolAddress((void**)&pAbar, g_Abar);
    cudaGetSymbolAddress((void**)&pOutBar, g_OutBar);
    cudaGetSymbolAddress((void**)&pw2, g_w2);
    cudaGetSymbolAddress((void**)&pv, g_vvec);
    cudaGetSymbolAddress((void**)&pXRs, g_XRs);
    cudaGetSymbolAddress((void**)&pYs, g_Ys);
    cudaGetSymbolAddress((void**)&pM3s, g_M3s);
    cudaGetSymbolAddress((void**)&pWkTs, g_WkTs);
    cudaGetSymbolAddress((void**)&pWqTs, g_WqTs);
    cudaGetSymbolAddress((void**)&pWvs, g_Wvs);
    cudaGetSymbolAddress((void**)&pWfcs, g_Wfcs);
    cudaGetSymbolAddress((void**)&pZs, g_Zs);
    cudaGetSymbolAddress((void**)&pObars, g_Obars);

    if (out_size >= RES_ELEMS + ATT_ELEMS) pAtt = out + RES_ELEMS;
    else cudaGetSymbolAddress((void**)&pAtt, g_Att);

    cudaFuncSetAttribute(gemm_mma_nt, cudaFuncAttributeMaxDynamicSharedMemorySize, DSM_BYTES);

    const float scale = rsqrtf((float)EE);
    const int nW = EE * EE;

    // 1) XR + canonical split (single pass over x)
    build_xr_split<<<MROWS, 256>>>(x, pXR, pXRs);

    // 2) M3 = Wk^T Wq  -> canonical split
    dim3 gT(64, 64);
    split3t<<<gT, 256>>>(Wk, pWkTs);
    split3t<<<gT, 256>>>(Wq, pWqTs);
    dim3 gM3(EE / 128, EE / 128);
    gemm_mma_nt<<<gM3, 256, DSM_BYTES>>>(pWkTs, pWqTs, nullptr, pM3s, 0, 0, 0, 0, 1.f, 1);

    // 3) Y = XR @ M3^T -> canonical split
    dim3 gY(EE / 128, MROWS / 128);
    gemm_mma_nt<<<gY, 256, DSM_BYTES>>>(pXRs, pM3s, nullptr, pYs, 0, 0, 0, 0, 1.f, 1);

    // 4) energy core = scale * Y_b XR_b^T  (batched over 32) -> fp32 att
    dim3 gE(512 / 128, 512 / 128, 32);
    gemm_mma_nt<<<gE, 256, DSM_BYTES>>>(pYs, pXRs, nullptr, pAtt, 512,
                                        (long long)512 * K2, (long long)512 * K2,
                                        (long long)512 * 512, scale, 0);

    // 5) bias column vector; softmax with +v[j]
    wkbq_kernel<<<EE / 256, 256>>>(Wk, bq, pw2);
    xrw2_kernel<<<MROWS / 8, 256>>>(pXR, pw2, pv, scale);
    softmax_rows<<<32 * 512, 128>>>(pAtt, pv);

    // 6) Abar, Z = Abar @ XR (canonical split emitted)
    abar_kernel<<<512, 512>>>(pAtt, pAbar);
    dim3 gZ(EE / 128, 32);
    zbar_split<<<gZ, 128>>>(pAbar, pXR, pZs);

    // 7) Obar = Z @ Wv^T + bv -> canonical split
    split3<<<(nW + 255) / 256, 256>>>(Wv, pWvs, nW);
    dim3 gOb(EE / 128, 512 / 128);
    gemm_mma_nt<<<gOb, 256, DSM_BYTES>>>(pZs, pWvs, bv, pObars, 0, 0, 0, 0, 1.f, 1);

    // 8) OutBar = Obar @ Wfc^T + bfc -> fp32
    split3<<<(nW + 255) / 256, 256>>>(Wfc, pWfcs, nW);
    gemm_mma_nt<<<gOb, 256, DSM_BYTES>>>(pObars, pWfcs, bfc, pOutBar, EE, 0, 0, 0, 1.f, 0);

    // 9) final output
    final_kernel<<<RES_ELEMS / 256, 256>>>(x, pOutBar, out);
}

// round 10
// speedup vs baseline: 3.6695x; 1.0010x over previous
#include <cuda_runtime.h>
#include <cuda_bf16.h>
#include <math.h>
#include <stdint.h>

// Problem dims
#define TT 16
#define BB 32
#define NN 512
#define FF 128
#define EE 2048            // F*T
#define K2 4096            // canonical split storage: [hi(2048) | lo(2048)]
#define NC 96              // K3=6144 virtual -> 96 chunks of 64 bf16
#define MROWS 16384        // B*N
#define ATT_ELEMS (32*512*512)
#define RES_ELEMS (16*512*128)

// ---------------- device scratch ----------------
__device__ float g_XR[(size_t)MROWS * EE];
__device__ float g_Att[(size_t)ATT_ELEMS];
__device__ float g_Abar[(size_t)512 * 512];
__device__ float g_OutBar[(size_t)512 * EE];
__device__ float g_w2[EE];
__device__ float g_vvec[MROWS];

// canonical split-bf16 buffers: row = [hi | lo], 4096 elems
__device__ __nv_bfloat16 g_XRs[(size_t)MROWS * K2];
__device__ __nv_bfloat16 g_Ys [(size_t)MROWS * K2];
__device__ __nv_bfloat16 g_M3s[(size_t)EE * K2];
__device__ __nv_bfloat16 g_WkTs[(size_t)EE * K2];
__device__ __nv_bfloat16 g_WqTs[(size_t)EE * K2];
__device__ __nv_bfloat16 g_Wvs [(size_t)EE * K2];
__device__ __nv_bfloat16 g_Wfcs[(size_t)EE * K2];
__device__ __nv_bfloat16 g_Zs  [(size_t)512 * K2];
__device__ __nv_bfloat16 g_Obars[(size_t)512 * K2];

// ================= helpers =================
__device__ __forceinline__ uint32_t smem_u32(const void* p) {
    uint32_t a;
    asm("{ .reg .u64 t; cvta.to.shared.u64 t, %1; cvt.u32.u64 %0, t; }" : "=r"(a) : "l"(p));
    return a;
}
#define SWZ128(off) ((off) ^ (((off) >> 3) & 0x70))

__device__ __forceinline__ void cp16(uint32_t s, const void* g) {
    asm volatile("cp.async.cg.shared.global [%0], [%1], 16;" :: "r"(s), "l"(g));
}
#define CP_COMMIT() asm volatile("cp.async.commit_group;" ::: "memory")
#define CP_WAIT1()  asm volatile("cp.async.wait_group 1;" ::: "memory")

__device__ __forceinline__ void ldmx4(uint32_t* f, uint32_t addr) {
    asm volatile("ldmatrix.sync.aligned.m8n8.x4.shared.b16 {%0,%1,%2,%3}, [%4];"
        : "=r"(f[0]), "=r"(f[1]), "=r"(f[2]), "=r"(f[3]) : "r"(addr));
}
__device__ __forceinline__ void mma16816(float* d, const uint32_t* a,
                                         uint32_t b0, uint32_t b1) {
    asm volatile("mma.sync.aligned.m16n8k16.row.col.f32.bf16.bf16.f32 "
        "{%0,%1,%2,%3}, {%4,%5,%6,%7}, {%8,%9}, {%0,%1,%2,%3};"
        : "+f"(d[0]), "+f"(d[1]), "+f"(d[2]), "+f"(d[3])
        : "r"(a[0]), "r"(a[1]), "r"(a[2]), "r"(a[3]), "r"(b0), "r"(b1));
}

// canonical split store: hi at p, lo at p+2048
__device__ __forceinline__ void store_split2(__nv_bfloat16* p, float x, float y) {
    __nv_bfloat162 h, l;
    h.x = __float2bfloat16(x); h.y = __float2bfloat16(y);
    l.x = __float2bfloat16(x - __bfloat162float(h.x));
    l.y = __float2bfloat16(y - __bfloat162float(h.y));
    *(__nv_bfloat162*)p = h;
    *(__nv_bfloat162*)(p + 2048) = l;
}

// chunk -> byte offset within canonical [hi|lo] row (8192 bytes)
// A operand pattern [H,L,H]; B operand pattern [H,H,L]
__device__ __forceinline__ int offA_of(int c) { return ((c < 64) ? c : c - 64) * 128; }
__device__ __forceinline__ int offB_of(int c) { return ((c < 32) ? c : c - 32) * 128; }

#define STAGE_BYTES 32768      // A 16KB + B 16KB (128 rows x 128B = 64 bf16 k-chunk)
#define NSTAGE 3
#define DSM_BYTES (NSTAGE * STAGE_BYTES + 128)

// ================= bf16 mma.sync NT GEMM (3-term split via chunk remap) ===========
// C = scale*(A3 @ B3^T) + bias; A3/B3 virtual K3=6144 split operands stored [R,4096].
// 128x128 tiles, 96 chunks, 3-stage cp.async ring, k-step register double buffering.
// emit: 0 -> fp32 C [Ncols, batched by sC]; 1 -> canonical split bf16 (ld=K2).
__global__ void __launch_bounds__(256, 2)
gemm_mma_nt(const __nv_bfloat16* __restrict__ A, const __nv_bfloat16* __restrict__ B,
            const float* __restrict__ bias, void* __restrict__ Cv,
            int Ncols, long long sA, long long sB, long long sC,
            float scale, int emit)
{
    extern __shared__ char sm[];
    A += (long long)blockIdx.z * sA;
    B += (long long)blockIdx.z * sB;

    const int tid = threadIdx.x, wid = tid >> 5, lane = tid & 31;
    const int row0 = blockIdx.y * 128, col0 = blockIdx.x * 128;
    const int wm = wid & 3, wn = wid >> 2;

    uint32_t sbase = (smem_u32(sm) + 127u) & ~127u;

    // loader mapping: row = tid>>1, 4 x 16B chunks starting at (tid&1)*4
    const int lrow = tid >> 1;
    const int lc0 = (tid & 1) * 4;
    const char* gA = (const char*)(A + (long long)(row0 + lrow) * K2);
    const char* gB = (const char*)(B + (long long)(col0 + lrow) * K2);
    uint32_t swo[4];
#pragma unroll
    for (int q = 0; q < 4; q++) {
        uint32_t off = (uint32_t)lrow * 128u + (lc0 + q) * 16u;
        swo[q] = SWZ128(off);
    }

    // prologue: chunks 0,1 -> stages 0,1
#pragma unroll
    for (int s = 0; s < 2; s++) {
        uint32_t aA = sbase + s * STAGE_BYTES;
        uint32_t aB = aA + 16384;
        int kb = s * 128;
#pragma unroll
        for (int q = 0; q < 4; q++) {
            cp16(aA + swo[q], gA + kb + (lc0 + q) * 16);
            cp16(aB + swo[q], gB + kb + (lc0 + q) * 16);
        }
        CP_COMMIT();
    }

    float acc[2][8][4];
#pragma unroll
    for (int mi = 0; mi < 2; mi++)
#pragma unroll
        for (int ni = 0; ni < 8; ni++)
#pragma unroll
            for (int r = 0; r < 4; r++) acc[mi][ni][r] = 0.f;

    const int fr = lane & 15;
    const int fk = (lane >> 4) * 16;
    uint32_t arow[2], brow[4];
#pragma unroll
    for (int mi = 0; mi < 2; mi++) arow[mi] = (uint32_t)(wm * 32 + mi * 16 + fr) * 128u;
#pragma unroll
    for (int bi = 0; bi < 4; bi++) brow[bi] = (uint32_t)(wn * 64 + bi * 16 + fr) * 128u;

    int st_c = 0, st_n = 2;
    for (int c = 0; c < NC; c++) {
        CP_WAIT1();               // chunk c resident
        __syncthreads();          // chunk c-1 consumed by all warps (stage st_n free)

        if (c + 2 < NC) {
            uint32_t aA = sbase + st_n * STAGE_BYTES;
            uint32_t aB = aA + 16384;
            int oA = offA_of(c + 2), oB = offB_of(c + 2);
#pragma unroll
            for (int q = 0; q < 4; q++) {
                cp16(aA + swo[q], gA + oA + (lc0 + q) * 16);
                cp16(aB + swo[q], gB + oB + (lc0 + q) * 16);
            }
        }
        CP_COMMIT();

        uint32_t aA = sbase + st_c * STAGE_BYTES;
        uint32_t aB = aA + 16384;

        // fragment buffers: af double-buffered per k-step; B as two fixed-role
        // 2-ldmatrix groups (bfA: n-tiles 0..3, bfB: n-tiles 4..7)
        uint32_t af[2][2][4];
        uint32_t bfA[2][4], bfB[2][4];

        // chunk fragment prologue: A(ks0) + bfA(ks0)
#pragma unroll
        for (int mi = 0; mi < 2; mi++)
            ldmx4(af[0][mi], aA + SWZ128(arow[mi] + fk));
#pragma unroll
        for (int p = 0; p < 2; p++)
            ldmx4(bfA[p], aB + SWZ128(brow[p] + fk));

#pragma unroll
        for (int ks = 0; ks < 4; ks++) {
            const int cur = ks & 1;
            const int kbyte = ks * 32 + fk;
            const int knext = kbyte + 32;

            // load bfB(ks) — consumed 8 MMAs from now
#pragma unroll
            for (int p = 0; p < 2; p++)
                ldmx4(bfB[p], aB + SWZ128(brow[2 + p] + kbyte));
            // load af(ks+1) — consumed 16 MMAs from now
            if (ks < 3) {
#pragma unroll
                for (int mi = 0; mi < 2; mi++)
                    ldmx4(af[cur ^ 1][mi], aA + SWZ128(arow[mi] + knext));
            }
            // compute n-tiles 0..3 with bfA(ks)
#pragma unroll
            for (int p = 0; p < 2; p++)
#pragma unroll
                for (int mi = 0; mi < 2; mi++) {
                    mma16816(acc[mi][2 * p + 0], af[cur][mi], bfA[p][0], bfA[p][2]);
                    mma16816(acc[mi][2 * p + 1], af[cur][mi], bfA[p][1], bfA[p][3]);
                }
            // load bfA(ks+1) — consumed 8 MMAs from now (next iteration's first half)
            if (ks < 3) {
#pragma unroll
                for (int p = 0; p < 2; p++)
                    ldmx4(bfA[p], aB + SWZ128(brow[p] + knext));
            }
            // compute n-tiles 4..7 with bfB(ks)
#pragma unroll
            for (int p = 0; p < 2; p++)
#pragma unroll
                for (int mi = 0; mi < 2; mi++) {
                    mma16816(acc[mi][4 + 2 * p + 0], af[cur][mi], bfB[p][0], bfB[p][2]);
                    mma16816(acc[mi][4 + 2 * p + 1], af[cur][mi], bfB[p][1], bfB[p][3]);
                }
        }
        st_c = (st_c == 2) ? 0 : st_c + 1;
        st_n = (st_n == 2) ? 0 : st_n + 1;
    }

    // epilogue
    if (emit == 0) {
        float* C = (float*)Cv + (long long)blockIdx.z * sC;
#pragma unroll
        for (int mi = 0; mi < 2; mi++) {
            int r = row0 + wm * 32 + mi * 16 + (lane >> 2);
#pragma unroll
            for (int ni = 0; ni < 8; ni++) {
                int cc = col0 + wn * 64 + ni * 8 + (lane & 3) * 2;
                float b0 = bias ? bias[cc] : 0.f;
                float b1 = bias ? bias[cc + 1] : 0.f;
                float2 v0, v1;
                v0.x = acc[mi][ni][0] * scale + b0;
                v0.y = acc[mi][ni][1] * scale + b1;
                v1.x = acc[mi][ni][2] * scale + b0;
                v1.y = acc[mi][ni][3] * scale + b1;
                *(float2*)(C + (long long)r * Ncols + cc) = v0;
                *(float2*)(C + (long long)(r + 8) * Ncols + cc) = v1;
            }
        }
    } else {
        __nv_bfloat16* C = (__nv_bfloat16*)Cv;
#pragma unroll
        for (int mi = 0; mi < 2; mi++) {
            int r = row0 + wm * 32 + mi * 16 + (lane >> 2);
#pragma unroll
            for (int ni = 0; ni < 8; ni++) {
                int cc = col0 + wn * 64 + ni * 8 + (lane & 3) * 2;
                float b0 = bias ? bias[cc] : 0.f;
                float b1 = bias ? bias[cc + 1] : 0.f;
                store_split2(C + (long long)r * K2 + cc,
                             acc[mi][ni][0] * scale + b0,
                             acc[mi][ni][1] * scale + b1);
                store_split2(C + (long long)(r + 8) * K2 + cc,
                             acc[mi][ni][2] * scale + b0,
                             acc[mi][ni][3] * scale + b1);
            }
        }
    }
}

// ================= elementwise kernels =================
__global__ void __launch_bounds__(256) split3(const float* __restrict__ X,
                                              __nv_bfloat16* __restrict__ Y, int n) {
    int i = blockIdx.x * 256 + threadIdx.x;
    if (i >= n) return;
    int r = i >> 11, k = i & 2047;
    float x = X[i];
    __nv_bfloat16 h = __float2bfloat16(x);
    __nv_bfloat16 l = __float2bfloat16(x - __bfloat162float(h));
    __nv_bfloat16* yr = Y + (size_t)r * K2;
    yr[k] = h;
    yr[2048 + k] = l;
}

__global__ void __launch_bounds__(256) split3t(const float* __restrict__ W,
                                               __nv_bfloat16* __restrict__ Y) {
    __shared__ float t[32][33];
    int tx = threadIdx.x & 31, ty = threadIdx.x >> 5;
    int cbase = blockIdx.x * 32;
    int rbase = blockIdx.y * 32;
#pragma unroll
    for (int j = 0; j < 4; j++)
        t[ty + j * 8][tx] = W[(size_t)(rbase + ty + j * 8) * EE + cbase + tx];
    __syncthreads();
#pragma unroll
    for (int j = 0; j < 4; j++) {
        int r = cbase + ty + j * 8;
        int k = rbase + tx;
        float x = t[tx][ty + j * 8];
        __nv_bfloat16 h = __float2bfloat16(x);
        __nv_bfloat16 l = __float2bfloat16(x - __bfloat162float(h));
        __nv_bfloat16* yr = Y + (size_t)r * K2;
        yr[k] = h;
        yr[2048 + k] = l;
    }
}

__global__ void __launch_bounds__(256) build_xr_split(const float* __restrict__ x,
                                                      float* __restrict__ xr,
                                                      __nv_bfloat16* __restrict__ xrs) {
    __shared__ float s[TT * 129];
    int bn = blockIdx.x;
    int b = bn >> 9, n = bn & 511;
    for (int i = threadIdx.x; i < TT * FF; i += 256) {
        int t = i >> 7, f = i & 127;
        s[t * 129 + f] = x[((size_t)(t * BB + b) * NN + n) * FF + f];
    }
    __syncthreads();
    for (int e = threadIdx.x; e < EE; e += 256) {
        int t = e & 15, f = e >> 4;
        float v = s[t * 129 + f];
        xr[(size_t)bn * EE + e] = v;
        __nv_bfloat16 h = __float2bfloat16(v);
        __nv_bfloat16 l = __float2bfloat16(v - __bfloat162float(h));
        size_t rb = (size_t)bn * K2 + e;
        xrs[rb] = h;
        xrs[rb + 2048] = l;
    }
}

__global__ void __launch_bounds__(256) wkbq_kernel(const float* __restrict__ Wk,
                                                   const float* __restrict__ bq,
                                                   float* __restrict__ w2) {
    int e = blockIdx.x * 256 + threadIdx.x;
    float s = 0.f;
    for (int d = 0; d < EE; d++) s += Wk[(size_t)d * EE + e] * bq[d];
    w2[e] = s;
}
__global__ void __launch_bounds__(256) xrw2_kernel(const float* __restrict__ XR,
                                                   const float* __restrict__ w2,
                                                   float* __restrict__ v, float scale) {
    int g = blockIdx.x * 8 + (threadIdx.x >> 5);
    int lane = threadIdx.x & 31;
    const float* r = XR + (size_t)g * EE;
    float s = 0.f;
    for (int e = lane; e < EE; e += 32) s += r[e] * w2[e];
#pragma unroll
    for (int o = 16; o; o >>= 1) s += __shfl_xor_sync(0xffffffffu, s, o);
    if (lane == 0) v[g] = s * scale;
}

__global__ void __launch_bounds__(128) softmax_rows(float* __restrict__ att,
                                                    const float* __restrict__ vadd) {
    size_t row = blockIdx.x;
    int b = (int)(row >> 9);
    float4* p = (float4*)(att + row * 512);
    const float4* vv = (const float4*)(vadd + (size_t)b * 512);
    float4 v = p[threadIdx.x];
    float4 a = vv[threadIdx.x];
    v.x += a.x; v.y += a.y; v.z += a.z; v.w += a.w;
    float m = fmaxf(fmaxf(v.x, v.y), fmaxf(v.z, v.w));
#pragma unroll
    for (int o = 16; o; o >>= 1) m = fmaxf(m, __shfl_xor_sync(0xffffffffu, m, o));
    __shared__ float sm[4];
    if ((threadIdx.x & 31) == 0) sm[threadIdx.x >> 5] = m;
    __syncthreads();
    m = fmaxf(fmaxf(sm[0], sm[1]), fmaxf(sm[2], sm[3]));
    v.x = __expf(v.x - m); v.y = __expf(v.y - m);
    v.z = __expf(v.z - m); v.w = __expf(v.w - m);
    float s = v.x + v.y + v.z + v.w;
#pragma unroll
    for (int o = 16; o; o >>= 1) s += __shfl_xor_sync(0xffffffffu, s, o);
    __shared__ float ss[4];
    if ((threadIdx.x & 31) == 0) ss[threadIdx.x >> 5] = s;
    __syncthreads();
    s = ss[0] + ss[1] + ss[2] + ss[3];
    float inv = 1.f / s;
    v.x *= inv; v.y *= inv; v.z *= inv; v.w *= inv;
    p[threadIdx.x] = v;
}

__global__ void __launch_bounds__(512) abar_kernel(const float* __restrict__ att,
                                                   float* __restrict__ abar) {
    int bg = blockIdx.x;
    int b = bg >> 4, g = bg & 15;
    const float* bse = att + ((size_t)b * 512 + g * 32) * 512;
    int j = threadIdx.x;
    float s = 0.f;
#pragma unroll 8
    for (int r = 0; r < 32; r++) s += bse[(size_t)r * 512 + j];
    abar[(size_t)bg * 512 + j] = s * (1.f / 32.f);
}

__global__ void __launch_bounds__(128) zbar_split(const float* __restrict__ abar,
                                                  const float* __restrict__ XR,
                                                  __nv_bfloat16* __restrict__ Zs) {
    int b = blockIdx.y;
    int col0 = blockIdx.x * 128;
    __shared__ float sA[16 * 512];
    for (int i = threadIdx.x; i < 16 * 512; i += 128)
        sA[i] = abar[(size_t)b * 16 * 512 + i];
    __syncthreads();
    float acc[16];
#pragma unroll
    for (int g = 0; g < 16; g++) acc[g] = 0.f;
    const float* vb = XR + (size_t)b * 512 * EE + col0 + threadIdx.x;
    for (int l = 0; l < 512; l++) {
        float vv = vb[(size_t)l * EE];
#pragma unroll
        for (int g = 0; g < 16; g++) acc[g] = fmaf(sA[g * 512 + l], vv, acc[g]);
    }
#pragma unroll
    for (int g = 0; g < 16; g++) {
        float v = acc[g];
        __nv_bfloat16 h = __float2bfloat16(v);
        __nv_bfloat16 l2 = __float2bfloat16(v - __bfloat162float(h));
        size_t rb = ((size_t)b * 16 + g) * K2 + col0 + threadIdx.x;
        Zs[rb] = h;
        Zs[rb + 2048] = l2;
    }
}

__global__ void __launch_bounds__(256) final_kernel(const float* __restrict__ x,
                                                    const float* __restrict__ outbar,
                                                    float* __restrict__ out) {
    int idx = blockIdx.x * 256 + threadIdx.x;
    int f = idx & 127;
    int i = (idx >> 7) & 511;
    int t = idx >> 16;
    const float* px = x + (size_t)t * (BB * NN * FF) + (size_t)i * FF + f;
    float s = 0.f;
#pragma unroll 8
    for (int b = 0; b < 32; b++) s += px[(size_t)b * (NN * FF)];
    out[idx] = s * (1.f / 32.f) + outbar[(size_t)i * EE + t * FF + f];
}

// ---------------- launcher ----------------
extern "C" void kernel_launch(void* const* d_in, const int* in_sizes, int n_in,
                              void* d_out, int out_size) {
    const float* x   = (const float*)d_in[0];
    const float* Wq  = (const float*)d_in[1];
    const float* bq  = (const float*)d_in[2];
    const float* Wk  = (const float*)d_in[3];
    const float* Wv  = (const float*)d_in[5];
    const float* bv  = (const float*)d_in[6];
    const float* Wfc = (const float*)d_in[7];
    const float* bfc = (const float*)d_in[8];
    float* out = (float*)d_out;

    float *pXR, *pAtt, *pAbar, *pOutBar, *pw2, *pv;
    __nv_bfloat16 *pXRs, *pYs, *pM3s, *pWkTs, *pWqTs, *pWvs, *pWfcs, *pZs, *pObars;
    cudaGetSymbolAddress((void**)&pXR, g_XR);
    cudaGetSymbolAddress((void**)&pAbar, g_Abar);
    cudaGetSymbolAddress((void**)&pOutBar, g_OutBar);
    cudaGetSymbolAddress((void**)&pw2, g_w2);
    cudaGetSymbolAddress((void**)&pv, g_vvec);
    cudaGetSymbolAddress((void**)&pXRs, g_XRs);
    cudaGetSymbolAddress((void**)&pYs, g_Ys);
    cudaGetSymbolAddress((void**)&pM3s, g_M3s);
    cudaGetSymbolAddress((void**)&pWkTs, g_WkTs);
    cudaGetSymbolAddress((void**)&pWqTs, g_WqTs);
    cudaGetSymbolAddress((void**)&pWvs, g_Wvs);
    cudaGetSymbolAddress((void**)&pWfcs, g_Wfcs);
    cudaGetSymbolAddress((void**)&pZs, g_Zs);
    cudaGetSymbolAddress((void**)&pObars, g_Obars);

    if (out_size >= RES_ELEMS + ATT_ELEMS) pAtt = out + RES_ELEMS;
    else cudaGetSymbolAddress((void**)&pAtt, g_Att);

    cudaFuncSetAttribute(gemm_mma_nt, cudaFuncAttributeMaxDynamicSharedMemorySize, DSM_BYTES);

    const float scale = rsqrtf((float)EE);
    const int nW = EE * EE;

    // 1) XR + canonical split (single pass over x)
    build_xr_split<<<MROWS, 256>>>(x, pXR, pXRs);

    // 2) M3 = Wk^T Wq  -> canonical split
    dim3 gT(64, 64);
    split3t<<<gT, 256>>>(Wk, pWkTs);
    split3t<<<gT, 256>>>(Wq, pWqTs);
    dim3 gM3(EE / 128, EE / 128);
    gemm_mma_nt<<<gM3, 256, DSM_BYTES>>>(pWkTs, pWqTs, nullptr, pM3s, 0, 0, 0, 0, 1.f, 1);

    // 3) Y = XR @ M3^T -> canonical split
    dim3 gY(EE / 128, MROWS / 128);
    gemm_mma_nt<<<gY, 256, DSM_BYTES>>>(pXRs, pM3s, nullptr, pYs, 0, 0, 0, 0, 1.f, 1);

    // 4) energy core = scale * Y_b XR_b^T  (batched over 32) -> fp32 att
    dim3 gE(512 / 128, 512 / 128, 32);
    gemm_mma_nt<<<gE, 256, DSM_BYTES>>>(pYs, pXRs, nullptr, pAtt, 512,
                                        (long long)512 * K2, (long long)512 * K2,
                                        (long long)512 * 512, scale, 0);

    // 5) bias column vector; softmax with +v[j]
    wkbq_kernel<<<EE / 256, 256>>>(Wk, bq, pw2);
    xrw2_kernel<<<MROWS / 8, 256>>>(pXR, pw2, pv, scale);
    softmax_rows<<<32 * 512, 128>>>(pAtt, pv);

    // 6) Abar, Z = Abar @ XR (canonical split emitted)
    abar_kernel<<<512, 512>>>(pAtt, pAbar);
    dim3 gZ(EE / 128, 32);
    zbar_split<<<gZ, 128>>>(pAbar, pXR, pZs);

    // 7) Obar = Z @ Wv^T + bv -> canonical split
    split3<<<(nW + 255) / 256, 256>>>(Wv, pWvs, nW);
    dim3 gOb(EE / 128, 512 / 128);
    gemm_mma_nt<<<gOb, 256, DSM_BYTES>>>(pZs, pWvs, bv, pObars, 0, 0, 0, 0, 1.f, 1);

    // 8) OutBar = Obar @ Wfc^T + bfc -> fp32
    split3<<<(nW + 255) / 256, 256>>>(Wfc, pWfcs, nW);
    gemm_mma_nt<<<gOb, 256, DSM_BYTES>>>(pObars, pWfcs, bfc, pOutBar, EE, 0, 0, 0, 1.f, 0);

    // 9) final output
    final_kernel<<<RES_ELEMS / 256, 256>>>(x, pOutBar, out);
}